// round 1
// baseline (speedup 1.0000x reference)
#include <cuda_runtime.h>
#include <cstdint>

// ---------------------------------------------------------------------------
// CrystalDecoder: B=256 graphs, N nodes, E edges, LATENT=32, HID=64 (2H=128)
// Inputs (metadata order):
//  0 z[B,32] 1 node_emb[N,128] 2 graph_id[N] 3 src[E] 4 dst[E]
//  5 lp_w[32,128] 6 lp_b[128] 7 nep_w[128,128] 8 nep_b[128]
//  9 nd1_w[128,64] 10 nd1_b[64] 11 nd2_w[64,4] 12 nd2_b[4]
// 13 ed1_w[256,64] 14 ed1_b[64] 15 ed2_w[64,3] 16 ed2_b[3]
// 17 en1_w[32,64] 18 en1_b[64] 19 en2_w[64,2] 20 en2_b[2]
// 21 st1_w[32,64] 22 st1_b[64] 23 st2_w[64,9] 24 st2_b[9]
// Output: [recon_node N*4 | recon_edge E*3 | energy B*2 | stress B*9]
// ---------------------------------------------------------------------------

#define MAXB 256

__device__ float  g_zb[MAXB * 64];      // z_proj @ nd1_w  (per-graph bias for node L2)
__device__ float  g_As[MAXB * 64];      // z_proj @ ed1_w[:128]
__device__ float  g_Bd[MAXB * 64];      // z_proj @ ed1_w[128:]
__device__ float4 g_table[MAXB * MAXB]; // per (gs,gd) edge output (xyz used)

// ---- packed fp32x2 helpers (sm_100+) --------------------------------------
__device__ __forceinline__ unsigned long long pk2(float lo, float hi) {
    unsigned long long r;
    asm("mov.b64 %0, {%1, %2};" : "=l"(r) : "f"(lo), "f"(hi));
    return r;
}
__device__ __forceinline__ void fma2(unsigned long long& d,
                                     unsigned long long a, unsigned long long b) {
    asm("fma.rn.f32x2 %0, %1, %2, %0;" : "+l"(d) : "l"(a), "l"(b));
}
__device__ __forceinline__ float2 upk2(unsigned long long v) {
    float2 r;
    asm("mov.b64 {%0, %1}, %2;" : "=f"(r.x), "=f"(r.y) : "l"(v));
    return r;
}

// ---------------------------------------------------------------------------
// Kernel A: per-graph prep. grid = B, block = 128.
//   z_proj = relu(z@lp_w+lp_b); As/Bd = z_proj @ ed1_w halves; zb = z_proj@nd1_w
//   pred_energy, pred_stress written directly to output.
// ---------------------------------------------------------------------------
__global__ void prep_kernel(const float* __restrict__ z,
                            const float* __restrict__ lp_w, const float* __restrict__ lp_b,
                            const float* __restrict__ nd1_w,
                            const float* __restrict__ ed1_w,
                            const float* __restrict__ en1_w, const float* __restrict__ en1_b,
                            const float* __restrict__ en2_w, const float* __restrict__ en2_b,
                            const float* __restrict__ st1_w, const float* __restrict__ st1_b,
                            const float* __restrict__ st2_w, const float* __restrict__ st2_b,
                            float* __restrict__ out_energy, float* __restrict__ out_stress)
{
    const int b = blockIdx.x;
    const int t = threadIdx.x; // 0..127
    __shared__ float zrow[32];
    __shared__ float zp[128];
    __shared__ float eh[64], sh[64];

    if (t < 32) zrow[t] = z[b * 32 + t];
    __syncthreads();

    // z_proj (all 128 threads)
    {
        float acc = lp_b[t];
        #pragma unroll
        for (int k = 0; k < 32; k++) acc = fmaf(zrow[k], lp_w[k * 128 + t], acc);
        zp[t] = fmaxf(acc, 0.f);
    }
    if (t < 64) {
        float a1 = en1_b[t], a2 = st1_b[t];
        #pragma unroll
        for (int k = 0; k < 32; k++) {
            float zv = zrow[k];
            a1 = fmaf(zv, en1_w[k * 64 + t], a1);
            a2 = fmaf(zv, st1_w[k * 64 + t], a2);
        }
        eh[t] = fmaxf(a1, 0.f);
        sh[t] = fmaxf(a2, 0.f);
    }
    __syncthreads();

    if (t < 64) {
        float as = 0.f, bd = 0.f, zb = 0.f;
        #pragma unroll 4
        for (int k = 0; k < 128; k++) {
            float zv = zp[k];
            as = fmaf(zv, ed1_w[k * 64 + t], as);
            bd = fmaf(zv, ed1_w[(128 + k) * 64 + t], bd);
            zb = fmaf(zv, nd1_w[k * 64 + t], zb);
        }
        g_As[b * 64 + t] = as;
        g_Bd[b * 64 + t] = bd;
        g_zb[b * 64 + t] = zb;
    }
    if (t < 2) {
        float a = en2_b[t];
        #pragma unroll 8
        for (int k = 0; k < 64; k++) a = fmaf(eh[k], en2_w[k * 2 + t], a);
        out_energy[b * 2 + t] = a;
    }
    if (t >= 16 && t < 25) {
        int j = t - 16;
        float a = st2_b[j];
        #pragma unroll 8
        for (int k = 0; k < 64; k++) a = fmaf(sh[k], st2_w[k * 9 + j], a);
        out_stress[b * 9 + j] = a;
    }
}

// ---------------------------------------------------------------------------
// Kernel B: edge lookup table. grid = B (gs), block = 256 (gd).
//   table[gs,gd] = relu(As[gs]+Bd[gd]+ed1_b) @ ed2_w + ed2_b
// ---------------------------------------------------------------------------
__global__ void edge_table_kernel(const float* __restrict__ ed1_b,
                                  const float* __restrict__ ed2_w,
                                  const float* __restrict__ ed2_b)
{
    const int gs = blockIdx.x;
    const int gd = threadIdx.x;
    __shared__ float sAs[64], sb1[64], sw2[64 * 3], sb2[3];
    const int t = threadIdx.x;
    if (t < 64) { sAs[t] = g_As[gs * 64 + t]; sb1[t] = ed1_b[t]; }
    if (t >= 64 && t < 64 + 192) sw2[t - 64] = ed2_w[t - 64];
    if (t < 3) sb2[t] = ed2_b[t];
    __syncthreads();

    float o0 = sb2[0], o1 = sb2[1], o2 = sb2[2];
    const float4* bd4 = (const float4*)(&g_Bd[gd * 64]);
    #pragma unroll
    for (int k4 = 0; k4 < 16; k4++) {
        float4 bv = bd4[k4];
        int k = k4 * 4;
        float h;
        h = fmaxf(sAs[k + 0] + bv.x + sb1[k + 0], 0.f);
        o0 = fmaf(h, sw2[(k + 0) * 3 + 0], o0); o1 = fmaf(h, sw2[(k + 0) * 3 + 1], o1); o2 = fmaf(h, sw2[(k + 0) * 3 + 2], o2);
        h = fmaxf(sAs[k + 1] + bv.y + sb1[k + 1], 0.f);
        o0 = fmaf(h, sw2[(k + 1) * 3 + 0], o0); o1 = fmaf(h, sw2[(k + 1) * 3 + 1], o1); o2 = fmaf(h, sw2[(k + 1) * 3 + 2], o2);
        h = fmaxf(sAs[k + 2] + bv.z + sb1[k + 2], 0.f);
        o0 = fmaf(h, sw2[(k + 2) * 3 + 0], o0); o1 = fmaf(h, sw2[(k + 2) * 3 + 1], o1); o2 = fmaf(h, sw2[(k + 2) * 3 + 2], o2);
        h = fmaxf(sAs[k + 3] + bv.w + sb1[k + 3], 0.f);
        o0 = fmaf(h, sw2[(k + 3) * 3 + 0], o0); o1 = fmaf(h, sw2[(k + 3) * 3 + 1], o1); o2 = fmaf(h, sw2[(k + 3) * 3 + 2], o2);
    }
    g_table[gs * MAXB + gd] = make_float4(o0, o1, o2, 0.f);
}

// ---------------------------------------------------------------------------
// Kernel C: node path. 128-node tile per block, 256 threads, fp32x2-packed GEMM.
//   t  = relu(X @ nep_w + nep_b)                [128 x 128]
//   h2 = relu(t @ nd1_w + zb[g] + nd1_b)        [128 x 64]
//   out = h2 @ nd2_w + nd2_b                    [128 x 4]
// ---------------------------------------------------------------------------
#define NODE_SMEM_FLOATS (128*128 + 128*128 + 128*64 + 128*65 + 64*4 + 128 + 64 + 4 + 128)
#define NODE_SMEM_BYTES  (NODE_SMEM_FLOATS * 4)

__global__ void __launch_bounds__(256, 1)
node_kernel(const float* __restrict__ node_emb, const int* __restrict__ graph_id,
            const float* __restrict__ w1, const float* __restrict__ b1,
            const float* __restrict__ w2, const float* __restrict__ b2,
            const float* __restrict__ w3, const float* __restrict__ b3,
            float* __restrict__ out_node, int N)
{
    extern __shared__ float sm[];
    float* sX  = sm;                   // [128][128] node-major; reused as sT after L1
    float* sW1 = sX  + 128 * 128;      // [128][128] k-major (row-major nep_w)
    float* sW2 = sW1 + 128 * 128;      // [128][64]
    float* sH  = sW2 + 128 * 64;       // [128][65] hidden2 (padded: conflict-free L3)
    float* sW3 = sH  + 128 * 65;       // [64][4]
    float* sB1 = sW3 + 64 * 4;         // [128]
    float* sB2 = sB1 + 128;            // [64]
    float* sB3 = sB2 + 64;             // [4]
    int*   sG  = (int*)(sB3 + 4);      // [128]

    const int tid  = threadIdx.x;
    const int base = blockIdx.x * 128;

    // -- stage weights / biases / graph ids --
    {
        const float4* w1v = (const float4*)w1;
        float4* d1 = (float4*)sW1;
        for (int i = tid; i < 128 * 128 / 4; i += 256) d1[i] = w1v[i];
        const float4* w2v = (const float4*)w2;
        float4* d2 = (float4*)sW2;
        for (int i = tid; i < 128 * 64 / 4; i += 256) d2[i] = w2v[i];
        if (tid < 64)  ((float4*)sW3)[tid] = ((const float4*)w3)[tid];
        sB1[tid & 127] = b1[tid & 127];   // 256 threads, 128 entries (dup write ok)
        if (tid < 64)  sB2[tid] = b2[tid];
        if (tid < 4)   sB3[tid] = b3[tid];
        if (tid < 128) {
            int n = base + tid;
            sG[tid] = (n < N) ? graph_id[n] : 0;
        }
    }
    // -- stage X tile (coalesced float4, node-major) --
    #pragma unroll
    for (int it = 0; it < 16; it++) {
        int idx = it * 256 + tid;      // 0..4095
        int n  = idx >> 5;             // 0..127 (constant per warp)
        int k4 = (idx & 31) << 2;      // 0..124
        int gn = base + n;
        float4 v = (gn < N) ? ((const float4*)(node_emb + (size_t)gn * 128))[k4 >> 2]
                            : make_float4(0.f, 0.f, 0.f, 0.f);
        *(float4*)&sX[n * 128 + k4] = v;
    }
    __syncthreads();

    const int tc = tid & 15;
    const int tn = tid >> 4;
    const int r0 = tn * 8;   // 8 rows per thread
    const int c0 = tc * 8;   // 8 cols (L1)
    const int c2 = tc * 4;   // 4 cols (L2)

    // ---- Layer 1: acc over col-pairs, f32x2 packed ----
    unsigned long long acc1[8][4];
    #pragma unroll
    for (int i = 0; i < 8; i++)
        #pragma unroll
        for (int q = 0; q < 4; q++) acc1[i][q] = 0ull;

    #pragma unroll 4
    for (int k = 0; k < 128; k++) {
        unsigned long long bq[4];
        #pragma unroll
        for (int q = 0; q < 4; q++)
            bq[q] = *(const unsigned long long*)&sW1[k * 128 + c0 + 2 * q];
        #pragma unroll
        for (int i = 0; i < 8; i++) {
            float a = sX[(r0 + i) * 128 + k];
            unsigned long long ap = pk2(a, a);
            #pragma unroll
            for (int q = 0; q < 4; q++) fma2(acc1[i][q], ap, bq[q]);
        }
    }
    __syncthreads();   // all sX reads done before overwrite

    // bias + relu -> sT (node-major, reuses sX)
    {
        float bb[8];
        #pragma unroll
        for (int j = 0; j < 8; j++) bb[j] = sB1[c0 + j];
        #pragma unroll
        for (int i = 0; i < 8; i++) {
            float2 v0 = upk2(acc1[i][0]);
            float2 v1 = upk2(acc1[i][1]);
            float2 v2 = upk2(acc1[i][2]);
            float2 v3 = upk2(acc1[i][3]);
            float4 lo = make_float4(fmaxf(v0.x + bb[0], 0.f), fmaxf(v0.y + bb[1], 0.f),
                                    fmaxf(v1.x + bb[2], 0.f), fmaxf(v1.y + bb[3], 0.f));
            float4 hi = make_float4(fmaxf(v2.x + bb[4], 0.f), fmaxf(v2.y + bb[5], 0.f),
                                    fmaxf(v3.x + bb[6], 0.f), fmaxf(v3.y + bb[7], 0.f));
            *(float4*)&sX[(r0 + i) * 128 + c0]     = lo;
            *(float4*)&sX[(r0 + i) * 128 + c0 + 4] = hi;
        }
    }
    __syncthreads();

    // ---- Layer 2 ----
    unsigned long long acc2[8][2];
    #pragma unroll
    for (int i = 0; i < 8; i++) { acc2[i][0] = 0ull; acc2[i][1] = 0ull; }

    #pragma unroll 4
    for (int k = 0; k < 128; k++) {
        unsigned long long bq0 = *(const unsigned long long*)&sW2[k * 64 + c2];
        unsigned long long bq1 = *(const unsigned long long*)&sW2[k * 64 + c2 + 2];
        #pragma unroll
        for (int i = 0; i < 8; i++) {
            float a = sX[(r0 + i) * 128 + k];
            unsigned long long ap = pk2(a, a);
            fma2(acc2[i][0], ap, bq0);
            fma2(acc2[i][1], ap, bq1);
        }
    }

    // zb gather + bias + relu -> sH
    {
        float bv0 = sB2[c2], bv1 = sB2[c2 + 1], bv2 = sB2[c2 + 2], bv3 = sB2[c2 + 3];
        #pragma unroll
        for (int i = 0; i < 8; i++) {
            int g = sG[r0 + i];
            float4 zb = *(const float4*)&g_zb[g * 64 + c2];
            float2 v0 = upk2(acc2[i][0]);
            float2 v1 = upk2(acc2[i][1]);
            float* hrow = &sH[(r0 + i) * 65 + c2];
            hrow[0] = fmaxf(v0.x + zb.x + bv0, 0.f);
            hrow[1] = fmaxf(v0.y + zb.y + bv1, 0.f);
            hrow[2] = fmaxf(v1.x + zb.z + bv2, 0.f);
            hrow[3] = fmaxf(v1.y + zb.w + bv3, 0.f);
        }
    }
    __syncthreads();

    // ---- Layer 3: one node per thread (threads 0..127) ----
    if (tid < 128) {
        int n = base + tid;
        float o0 = sB3[0], o1 = sB3[1], o2 = sB3[2], o3 = sB3[3];
        const float* h = &sH[tid * 65];
        #pragma unroll 8
        for (int k = 0; k < 64; k++) {
            float hv = h[k];
            const float* w = &sW3[k * 4];
            o0 = fmaf(hv, w[0], o0);
            o1 = fmaf(hv, w[1], o1);
            o2 = fmaf(hv, w[2], o2);
            o3 = fmaf(hv, w[3], o3);
        }
        if (n < N) *(float4*)&out_node[(size_t)n * 4] = make_float4(o0, o1, o2, o3);
    }
}

// ---------------------------------------------------------------------------
// Kernel D: edge gather (4 edges/thread, vectorized)
// ---------------------------------------------------------------------------
__global__ void edge_gather_kernel(const int* __restrict__ src, const int* __restrict__ dst,
                                   const int* __restrict__ graph_id,
                                   float* __restrict__ out_edge, int E)
{
    int e = (blockIdx.x * blockDim.x + threadIdx.x) * 4;
    if (e >= E) return;
    if (e + 4 <= E) {
        int4 s = *(const int4*)(src + e);
        int4 d = *(const int4*)(dst + e);
        float4 t0 = g_table[graph_id[s.x] * MAXB + graph_id[d.x]];
        float4 t1 = g_table[graph_id[s.y] * MAXB + graph_id[d.y]];
        float4 t2 = g_table[graph_id[s.z] * MAXB + graph_id[d.z]];
        float4 t3 = g_table[graph_id[s.w] * MAXB + graph_id[d.w]];
        float* o = out_edge + (size_t)e * 3;
        ((float4*)o)[0] = make_float4(t0.x, t0.y, t0.z, t1.x);
        ((float4*)o)[1] = make_float4(t1.y, t1.z, t2.x, t2.y);
        ((float4*)o)[2] = make_float4(t2.z, t3.x, t3.y, t3.z);
    } else {
        for (int q = e; q < E; q++) {
            float4 t = g_table[graph_id[src[q]] * MAXB + graph_id[dst[q]]];
            out_edge[(size_t)q * 3 + 0] = t.x;
            out_edge[(size_t)q * 3 + 1] = t.y;
            out_edge[(size_t)q * 3 + 2] = t.z;
        }
    }
}

// ---------------------------------------------------------------------------
extern "C" void kernel_launch(void* const* d_in, const int* in_sizes, int n_in,
                              void* d_out, int out_size)
{
    const float* z        = (const float*)d_in[0];
    const float* node_emb = (const float*)d_in[1];
    const int*   graph_id = (const int*)  d_in[2];
    const int*   src      = (const int*)  d_in[3];
    const int*   dst      = (const int*)  d_in[4];
    const float* lp_w  = (const float*)d_in[5];
    const float* lp_b  = (const float*)d_in[6];
    const float* nep_w = (const float*)d_in[7];
    const float* nep_b = (const float*)d_in[8];
    const float* nd1_w = (const float*)d_in[9];
    const float* nd1_b = (const float*)d_in[10];
    const float* nd2_w = (const float*)d_in[11];
    const float* nd2_b = (const float*)d_in[12];
    const float* ed1_w = (const float*)d_in[13];
    const float* ed1_b = (const float*)d_in[14];
    const float* ed2_w = (const float*)d_in[15];
    const float* ed2_b = (const float*)d_in[16];
    const float* en1_w = (const float*)d_in[17];
    const float* en1_b = (const float*)d_in[18];
    const float* en2_w = (const float*)d_in[19];
    const float* en2_b = (const float*)d_in[20];
    const float* st1_w = (const float*)d_in[21];
    const float* st1_b = (const float*)d_in[22];
    const float* st2_w = (const float*)d_in[23];
    const float* st2_b = (const float*)d_in[24];

    const int B = in_sizes[0] / 32;
    const int N = in_sizes[1] / 128;
    const int E = in_sizes[3];

    float* out        = (float*)d_out;
    float* out_node   = out;
    float* out_edge   = out + (size_t)N * 4;
    float* out_energy = out + (size_t)N * 4 + (size_t)E * 3;
    float* out_stress = out_energy + (size_t)B * 2;

    cudaFuncSetAttribute(node_kernel, cudaFuncAttributeMaxDynamicSharedMemorySize,
                         NODE_SMEM_BYTES);

    prep_kernel<<<B, 128>>>(z, lp_w, lp_b, nd1_w, ed1_w,
                            en1_w, en1_b, en2_w, en2_b,
                            st1_w, st1_b, st2_w, st2_b,
                            out_energy, out_stress);

    edge_table_kernel<<<B, 256>>>(ed1_b, ed2_w, ed2_b);

    const int nb = (N + 127) / 128;
    node_kernel<<<nb, 256, NODE_SMEM_BYTES>>>(node_emb, graph_id,
                                              nep_w, nep_b, nd1_w, nd1_b,
                                              nd2_w, nd2_b, out_node, N);

    const int eth = (E + 3) / 4;
    edge_gather_kernel<<<(eth + 255) / 256, 256>>>(src, dst, graph_id, out_edge, E);
}

// round 3
// speedup vs baseline: 1.6618x; 1.6618x over previous
#include <cuda_runtime.h>
#include <cuda_bf16.h>
#include <cstdint>

// ---------------------------------------------------------------------------
// CrystalDecoder on GB300 (sm_103a, compiled via compute_103 PTX -> no tcgen05)
// Node path: warp-level mma.sync bf16 hi/lo compensated GEMM (HMMA).
// Edge path: algebraic collapse to 256x256 lookup table + gather.
// ---------------------------------------------------------------------------

#define MAXB 256

__device__ float  g_zb[MAXB * 64];      // z_proj @ nd1_w
__device__ float  g_As[MAXB * 64];
__device__ float  g_Bd[MAXB * 64];
__device__ float4 g_table[MAXB * MAXB];

// pre-converted transposed weights, bf16 hi/lo: W1^T [128 n][128 k], W2^T [64 n][128 k]
__device__ uint16_t g_w1thi[128 * 128];
__device__ uint16_t g_w1tlo[128 * 128];
__device__ uint16_t g_w2thi[64 * 128];
__device__ uint16_t g_w2tlo[64 * 128];

// conflict-free padded strides (u32 words); stride ≡ 5 (mod 32) -> 5g+tg unique
#define XS 69
#define ZS 69

#define MMA16816(c, a, b0, b1) \
    asm volatile("mma.sync.aligned.m16n8k16.row.col.f32.bf16.bf16.f32 " \
        "{%0,%1,%2,%3}, {%4,%5,%6,%7}, {%8,%9}, {%0,%1,%2,%3};" \
        : "+f"((c)[0]), "+f"((c)[1]), "+f"((c)[2]), "+f"((c)[3]) \
        : "r"((a)[0]), "r"((a)[1]), "r"((a)[2]), "r"((a)[3]), "r"(b0), "r"(b1))

__device__ __forceinline__ uint32_t pkbf(float a, float b) {
    __nv_bfloat162 t = __floats2bfloat162_rn(a, b);
    return *(uint32_t*)&t;
}

// ---------------------------------------------------------------------------
// Weight conversion: w (k-major) -> transposed n-major bf16 hi/lo
// ---------------------------------------------------------------------------
__global__ void wconv_kernel(const float* __restrict__ w1, const float* __restrict__ w2)
{
    int i = blockIdx.x * blockDim.x + threadIdx.x;
    if (i < 128 * 128) {
        int k = i >> 7, n = i & 127;
        float v = w1[k * 128 + n];
        __nv_bfloat16 h = __float2bfloat16(v);
        __nv_bfloat16 l = __float2bfloat16(v - __bfloat162float(h));
        g_w1thi[n * 128 + k] = *(uint16_t*)&h;
        g_w1tlo[n * 128 + k] = *(uint16_t*)&l;
    }
    if (i < 64 * 128) {
        int k = i >> 6, n = i & 63;
        float v = w2[k * 64 + n];
        __nv_bfloat16 h = __float2bfloat16(v);
        __nv_bfloat16 l = __float2bfloat16(v - __bfloat162float(h));
        g_w2thi[n * 128 + k] = *(uint16_t*)&h;
        g_w2tlo[n * 128 + k] = *(uint16_t*)&l;
    }
}

// ---------------------------------------------------------------------------
// Persistent node kernel: 256 threads (8 warps x M16), 128-node tiles.
//   L1: C1[128,128] = Xhi*W1hi + Xhi*W1lo + Xlo*W1hi   (mma.sync bf16)
//   L2: C2[128,64]  = A2hi*W2hi + A2hi*W2lo + A2lo*W2hi, A2 built in registers
//   L3: 64->4 scalar FMA + shfl reduce
// ---------------------------------------------------------------------------
#define NODE_SMEM_U32 (2*128*XS /*W1*/ + 2*64*XS /*W2*/ + 2*128*XS /*X*/ + 128*ZS /*zb*/ \
                       + 128 /*b1*/ + 64 /*b2*/ + 256 /*w3*/ + 128 /*gid*/)
#define NODE_SMEM_BYTES (NODE_SMEM_U32 * 4)

__global__ void __launch_bounds__(256, 1)
node_mma_kernel(const float* __restrict__ node_emb, const int* __restrict__ graph_id,
                const float* __restrict__ b1, const float* __restrict__ b2,
                const float* __restrict__ w3, const float* __restrict__ b3,
                float* __restrict__ out_node, int N, int ntiles)
{
    extern __shared__ uint32_t su[];
    uint32_t* sW1h = su;                        // [128][XS]
    uint32_t* sW1l = sW1h + 128 * XS;
    uint32_t* sW2h = sW1l + 128 * XS;           // [64][XS]
    uint32_t* sW2l = sW2h + 64 * XS;
    uint32_t* sXh  = sW2l + 64 * XS;            // [128][XS]
    uint32_t* sXl  = sXh + 128 * XS;
    float*    szb  = (float*)(sXl + 128 * XS);  // [128][ZS]
    float*    sB1  = szb + 128 * ZS;            // [128]
    float*    sB2  = sB1 + 128;                 // [64]
    float*    sW3  = sB2 + 64;                  // [64][4]
    int*      sG   = (int*)(sW3 + 256);         // [128]

    const int tid  = threadIdx.x;
    const int lane = tid & 31;
    const int w    = tid >> 5;
    const int g    = lane >> 2;
    const int tg   = lane & 3;
    const int r0   = w * 16;

    // ---- one-time staging ----
    for (int i = tid; i < 128 * 64; i += 256) {
        int n = i >> 6, kp = i & 63;
        sW1h[n * XS + kp] = ((const uint32_t*)g_w1thi)[i];
        sW1l[n * XS + kp] = ((const uint32_t*)g_w1tlo)[i];
    }
    for (int i = tid; i < 64 * 64; i += 256) {
        int n = i >> 6, kp = i & 63;
        sW2h[n * XS + kp] = ((const uint32_t*)g_w2thi)[i];
        sW2l[n * XS + kp] = ((const uint32_t*)g_w2tlo)[i];
    }
    if (tid < 128) sB1[tid] = b1[tid];
    if (tid < 64)  sB2[tid] = b2[tid];
    if (tid < 64)  ((float4*)sW3)[tid] = ((const float4*)w3)[tid];
    const float b30 = b3[0], b31 = b3[1], b32 = b3[2], b33 = b3[3];
    __syncthreads();

    for (int tile = blockIdx.x; tile < ntiles; tile += gridDim.x) {
        const int base = tile * 128;

        // ---- stage gid + X (bf16 hi/lo split, coalesced float4 loads) ----
        if (tid < 128) {
            int n = base + tid;
            sG[tid] = (n < N) ? graph_id[n] : 0;
        }
        #pragma unroll
        for (int it = 0; it < 16; it++) {
            int idx = it * 256 + tid;        // 0..4095
            int n = idx >> 5;                // row 0..127
            int q = idx & 31;                // float4 index
            int gn = base + n;
            float4 v = (gn < N) ? ((const float4*)(node_emb + (size_t)gn * 128))[q]
                                : make_float4(0.f, 0.f, 0.f, 0.f);
            float hx = __bfloat162float(__float2bfloat16(v.x));
            float hy = __bfloat162float(__float2bfloat16(v.y));
            float hz = __bfloat162float(__float2bfloat16(v.z));
            float hw = __bfloat162float(__float2bfloat16(v.w));
            sXh[n * XS + 2 * q]     = pkbf(hx, hy);
            sXh[n * XS + 2 * q + 1] = pkbf(hz, hw);
            sXl[n * XS + 2 * q]     = pkbf(v.x - hx, v.y - hy);
            sXl[n * XS + 2 * q + 1] = pkbf(v.z - hz, v.w - hw);
        }
        __syncthreads();

        // ---- stage zb (needs sG; synced above) ----
        #pragma unroll
        for (int it = 0; it < 8; it++) {
            int i = it * 256 + tid;          // 0..2047
            int row = i >> 4;
            int c4  = i & 15;
            int gid = sG[row];
            float4 zv = ((const float4*)(g_zb + gid * 64))[c4];
            float4 bb = ((const float4*)sB2)[c4];
            float* d = &szb[row * ZS + c4 * 4];
            d[0] = zv.x + bb.x; d[1] = zv.y + bb.y;
            d[2] = zv.z + bb.z; d[3] = zv.w + bb.w;
        }
        __syncthreads();

        // ---- load A fragments (rows r0..r0+15) ----
        uint32_t ah[8][4], al[8][4];
        #pragma unroll
        for (int s = 0; s < 8; s++) {
            int o = s * 8 + tg;
            ah[s][0] = sXh[(r0 + g) * XS + o];
            ah[s][1] = sXh[(r0 + g + 8) * XS + o];
            ah[s][2] = sXh[(r0 + g) * XS + o + 4];
            ah[s][3] = sXh[(r0 + g + 8) * XS + o + 4];
            al[s][0] = sXl[(r0 + g) * XS + o];
            al[s][1] = sXl[(r0 + g + 8) * XS + o];
            al[s][2] = sXl[(r0 + g) * XS + o + 4];
            al[s][3] = sXl[(r0 + g + 8) * XS + o + 4];
        }

        // ---- Layer 1: 16 n-tiles x 8 k-steps x 3 compensated MMAs ----
        float acc[16][4];
        #pragma unroll
        for (int nt = 0; nt < 16; nt++)
            #pragma unroll
            for (int j = 0; j < 4; j++) acc[nt][j] = 0.f;

        #pragma unroll
        for (int nt = 0; nt < 16; nt++) {
            const int nrow = (nt * 8 + g) * XS;
            #pragma unroll
            for (int s = 0; s < 8; s++) {
                int o = s * 8 + tg;
                uint32_t bh0 = sW1h[nrow + o];
                uint32_t bh1 = sW1h[nrow + o + 4];
                uint32_t bl0 = sW1l[nrow + o];
                uint32_t bl1 = sW1l[nrow + o + 4];
                MMA16816(acc[nt], ah[s], bh0, bh1);
                MMA16816(acc[nt], ah[s], bl0, bl1);
                MMA16816(acc[nt], al[s], bh0, bh1);
            }
        }

        // ---- epilogue 1 (in registers): bias+relu, bf16 hi/lo -> A2 frags ----
        uint32_t a2h[8][4], a2l[8][4];
        #pragma unroll
        for (int s2 = 0; s2 < 8; s2++) {
            int cA = s2 * 16 + tg * 2;   // cols of acc[2*s2]
            int cB = cA + 8;             // cols of acc[2*s2+1]
            float bA0 = sB1[cA], bA1 = sB1[cA + 1];
            float bB0 = sB1[cB], bB1 = sB1[cB + 1];
            // reg 0: row g, k = cA
            {
                float x0 = fmaxf(acc[2 * s2][0] + bA0, 0.f);
                float x1 = fmaxf(acc[2 * s2][1] + bA1, 0.f);
                float h0 = __bfloat162float(__float2bfloat16(x0));
                float h1 = __bfloat162float(__float2bfloat16(x1));
                a2h[s2][0] = pkbf(h0, h1);
                a2l[s2][0] = pkbf(x0 - h0, x1 - h1);
            }
            // reg 1: row g+8, k = cA
            {
                float x0 = fmaxf(acc[2 * s2][2] + bA0, 0.f);
                float x1 = fmaxf(acc[2 * s2][3] + bA1, 0.f);
                float h0 = __bfloat162float(__float2bfloat16(x0));
                float h1 = __bfloat162float(__float2bfloat16(x1));
                a2h[s2][1] = pkbf(h0, h1);
                a2l[s2][1] = pkbf(x0 - h0, x1 - h1);
            }
            // reg 2: row g, k = cB
            {
                float x0 = fmaxf(acc[2 * s2 + 1][0] + bB0, 0.f);
                float x1 = fmaxf(acc[2 * s2 + 1][1] + bB1, 0.f);
                float h0 = __bfloat162float(__float2bfloat16(x0));
                float h1 = __bfloat162float(__float2bfloat16(x1));
                a2h[s2][2] = pkbf(h0, h1);
                a2l[s2][2] = pkbf(x0 - h0, x1 - h1);
            }
            // reg 3: row g+8, k = cB
            {
                float x0 = fmaxf(acc[2 * s2 + 1][2] + bB0, 0.f);
                float x1 = fmaxf(acc[2 * s2 + 1][3] + bB1, 0.f);
                float h0 = __bfloat162float(__float2bfloat16(x0));
                float h1 = __bfloat162float(__float2bfloat16(x1));
                a2h[s2][3] = pkbf(h0, h1);
                a2l[s2][3] = pkbf(x0 - h0, x1 - h1);
            }
        }

        // ---- Layer 2: 8 n-tiles x 8 k-steps x 3 MMAs ----
        float acc2[8][4];
        #pragma unroll
        for (int nt = 0; nt < 8; nt++)
            #pragma unroll
            for (int j = 0; j < 4; j++) acc2[nt][j] = 0.f;

        #pragma unroll
        for (int nt = 0; nt < 8; nt++) {
            const int nrow = (nt * 8 + g) * XS;
            #pragma unroll
            for (int s = 0; s < 8; s++) {
                int o = s * 8 + tg;
                uint32_t bh0 = sW2h[nrow + o];
                uint32_t bh1 = sW2h[nrow + o + 4];
                uint32_t bl0 = sW2l[nrow + o];
                uint32_t bl1 = sW2l[nrow + o + 4];
                MMA16816(acc2[nt], a2h[s], bh0, bh1);
                MMA16816(acc2[nt], a2h[s], bl0, bl1);
                MMA16816(acc2[nt], a2l[s], bh0, bh1);
            }
        }

        // ---- epilogue 2: zb+b2, relu, L3 (64->4), shfl reduce, store ----
        {
            const int rA = r0 + g;
            const int rB = rA + 8;
            float oA0 = 0.f, oA1 = 0.f, oA2 = 0.f, oA3 = 0.f;
            float oB0 = 0.f, oB1 = 0.f, oB2 = 0.f, oB3 = 0.f;
            #pragma unroll
            for (int nt = 0; nt < 8; nt++) {
                int c0 = nt * 8 + tg * 2;
                int c1 = c0 + 1;
                float hA0 = fmaxf(acc2[nt][0] + szb[rA * ZS + c0], 0.f);
                float hA1 = fmaxf(acc2[nt][1] + szb[rA * ZS + c1], 0.f);
                float hB0 = fmaxf(acc2[nt][2] + szb[rB * ZS + c0], 0.f);
                float hB1 = fmaxf(acc2[nt][3] + szb[rB * ZS + c1], 0.f);
                float4 w0 = *(const float4*)&sW3[c0 * 4];
                float4 w1 = *(const float4*)&sW3[c1 * 4];
                oA0 = fmaf(hA0, w0.x, fmaf(hA1, w1.x, oA0));
                oA1 = fmaf(hA0, w0.y, fmaf(hA1, w1.y, oA1));
                oA2 = fmaf(hA0, w0.z, fmaf(hA1, w1.z, oA2));
                oA3 = fmaf(hA0, w0.w, fmaf(hA1, w1.w, oA3));
                oB0 = fmaf(hB0, w0.x, fmaf(hB1, w1.x, oB0));
                oB1 = fmaf(hB0, w0.y, fmaf(hB1, w1.y, oB1));
                oB2 = fmaf(hB0, w0.z, fmaf(hB1, w1.z, oB2));
                oB3 = fmaf(hB0, w0.w, fmaf(hB1, w1.w, oB3));
            }
            #pragma unroll
            for (int d = 1; d <= 2; d <<= 1) {
                oA0 += __shfl_xor_sync(0xFFFFFFFF, oA0, d);
                oA1 += __shfl_xor_sync(0xFFFFFFFF, oA1, d);
                oA2 += __shfl_xor_sync(0xFFFFFFFF, oA2, d);
                oA3 += __shfl_xor_sync(0xFFFFFFFF, oA3, d);
                oB0 += __shfl_xor_sync(0xFFFFFFFF, oB0, d);
                oB1 += __shfl_xor_sync(0xFFFFFFFF, oB1, d);
                oB2 += __shfl_xor_sync(0xFFFFFFFF, oB2, d);
                oB3 += __shfl_xor_sync(0xFFFFFFFF, oB3, d);
            }
            if (tg == 0) {
                int nA = base + rA;
                if (nA < N)
                    *(float4*)&out_node[(size_t)nA * 4] =
                        make_float4(oA0 + b30, oA1 + b31, oA2 + b32, oA3 + b33);
                int nB = base + rB;
                if (nB < N)
                    *(float4*)&out_node[(size_t)nB * 4] =
                        make_float4(oB0 + b30, oB1 + b31, oB2 + b32, oB3 + b33);
            }
        }
        __syncthreads();   // before sX/szb overwrite next tile
    }
}

// ---------------------------------------------------------------------------
// Per-graph prep (unchanged from R1)
// ---------------------------------------------------------------------------
__global__ void prep_kernel(const float* __restrict__ z,
                            const float* __restrict__ lp_w, const float* __restrict__ lp_b,
                            const float* __restrict__ nd1_w,
                            const float* __restrict__ ed1_w,
                            const float* __restrict__ en1_w, const float* __restrict__ en1_b,
                            const float* __restrict__ en2_w, const float* __restrict__ en2_b,
                            const float* __restrict__ st1_w, const float* __restrict__ st1_b,
                            const float* __restrict__ st2_w, const float* __restrict__ st2_b,
                            float* __restrict__ out_energy, float* __restrict__ out_stress)
{
    const int b = blockIdx.x;
    const int t = threadIdx.x;
    __shared__ float zrow[32];
    __shared__ float zp[128];
    __shared__ float eh[64], sh[64];

    if (t < 32) zrow[t] = z[b * 32 + t];
    __syncthreads();
    {
        float acc = lp_b[t];
        #pragma unroll
        for (int k = 0; k < 32; k++) acc = fmaf(zrow[k], lp_w[k * 128 + t], acc);
        zp[t] = fmaxf(acc, 0.f);
    }
    if (t < 64) {
        float a1 = en1_b[t], a2 = st1_b[t];
        #pragma unroll
        for (int k = 0; k < 32; k++) {
            float zv = zrow[k];
            a1 = fmaf(zv, en1_w[k * 64 + t], a1);
            a2 = fmaf(zv, st1_w[k * 64 + t], a2);
        }
        eh[t] = fmaxf(a1, 0.f);
        sh[t] = fmaxf(a2, 0.f);
    }
    __syncthreads();
    if (t < 64) {
        float as = 0.f, bd = 0.f, zb = 0.f;
        #pragma unroll 4
        for (int k = 0; k < 128; k++) {
            float zv = zp[k];
            as = fmaf(zv, ed1_w[k * 64 + t], as);
            bd = fmaf(zv, ed1_w[(128 + k) * 64 + t], bd);
            zb = fmaf(zv, nd1_w[k * 64 + t], zb);
        }
        g_As[b * 64 + t] = as;
        g_Bd[b * 64 + t] = bd;
        g_zb[b * 64 + t] = zb;
    }
    if (t < 2) {
        float a = en2_b[t];
        #pragma unroll 8
        for (int k = 0; k < 64; k++) a = fmaf(eh[k], en2_w[k * 2 + t], a);
        out_energy[b * 2 + t] = a;
    }
    if (t >= 16 && t < 25) {
        int j = t - 16;
        float a = st2_b[j];
        #pragma unroll 8
        for (int k = 0; k < 64; k++) a = fmaf(sh[k], st2_w[k * 9 + j], a);
        out_stress[b * 9 + j] = a;
    }
}

// ---------------------------------------------------------------------------
// Edge table (unchanged)
// ---------------------------------------------------------------------------
__global__ void edge_table_kernel(const float* __restrict__ ed1_b,
                                  const float* __restrict__ ed2_w,
                                  const float* __restrict__ ed2_b)
{
    const int gs = blockIdx.x;
    const int gd = threadIdx.x;
    __shared__ float sAs[64], sb1[64], sw2[64 * 3], sb2[3];
    const int t = threadIdx.x;
    if (t < 64) { sAs[t] = g_As[gs * 64 + t]; sb1[t] = ed1_b[t]; }
    if (t >= 64 && t < 64 + 192) sw2[t - 64] = ed2_w[t - 64];
    if (t < 3) sb2[t] = ed2_b[t];
    __syncthreads();

    float o0 = sb2[0], o1 = sb2[1], o2 = sb2[2];
    const float4* bd4 = (const float4*)(&g_Bd[gd * 64]);
    #pragma unroll
    for (int k4 = 0; k4 < 16; k4++) {
        float4 bv = bd4[k4];
        int k = k4 * 4;
        float h;
        h = fmaxf(sAs[k + 0] + bv.x + sb1[k + 0], 0.f);
        o0 = fmaf(h, sw2[(k + 0) * 3 + 0], o0); o1 = fmaf(h, sw2[(k + 0) * 3 + 1], o1); o2 = fmaf(h, sw2[(k + 0) * 3 + 2], o2);
        h = fmaxf(sAs[k + 1] + bv.y + sb1[k + 1], 0.f);
        o0 = fmaf(h, sw2[(k + 1) * 3 + 0], o0); o1 = fmaf(h, sw2[(k + 1) * 3 + 1], o1); o2 = fmaf(h, sw2[(k + 1) * 3 + 2], o2);
        h = fmaxf(sAs[k + 2] + bv.z + sb1[k + 2], 0.f);
        o0 = fmaf(h, sw2[(k + 2) * 3 + 0], o0); o1 = fmaf(h, sw2[(k + 2) * 3 + 1], o1); o2 = fmaf(h, sw2[(k + 2) * 3 + 2], o2);
        h = fmaxf(sAs[k + 3] + bv.w + sb1[k + 3], 0.f);
        o0 = fmaf(h, sw2[(k + 3) * 3 + 0], o0); o1 = fmaf(h, sw2[(k + 3) * 3 + 1], o1); o2 = fmaf(h, sw2[(k + 3) * 3 + 2], o2);
    }
    g_table[gs * MAXB + gd] = make_float4(o0, o1, o2, 0.f);
}

// ---------------------------------------------------------------------------
// Edge gather (unchanged; L2-latency bound at ~23us)
// ---------------------------------------------------------------------------
__global__ void edge_gather_kernel(const int* __restrict__ src, const int* __restrict__ dst,
                                   const int* __restrict__ graph_id,
                                   float* __restrict__ out_edge, int E)
{
    int e = (blockIdx.x * blockDim.x + threadIdx.x) * 4;
    if (e >= E) return;
    if (e + 4 <= E) {
        int4 s = *(const int4*)(src + e);
        int4 d = *(const int4*)(dst + e);
        float4 t0 = g_table[graph_id[s.x] * MAXB + graph_id[d.x]];
        float4 t1 = g_table[graph_id[s.y] * MAXB + graph_id[d.y]];
        float4 t2 = g_table[graph_id[s.z] * MAXB + graph_id[d.z]];
        float4 t3 = g_table[graph_id[s.w] * MAXB + graph_id[d.w]];
        float* o = out_edge + (size_t)e * 3;
        ((float4*)o)[0] = make_float4(t0.x, t0.y, t0.z, t1.x);
        ((float4*)o)[1] = make_float4(t1.y, t1.z, t2.x, t2.y);
        ((float4*)o)[2] = make_float4(t2.z, t3.x, t3.y, t3.z);
    } else {
        for (int q = e; q < E; q++) {
            float4 t = g_table[graph_id[src[q]] * MAXB + graph_id[dst[q]]];
            out_edge[(size_t)q * 3 + 0] = t.x;
            out_edge[(size_t)q * 3 + 1] = t.y;
            out_edge[(size_t)q * 3 + 2] = t.z;
        }
    }
}

// ---------------------------------------------------------------------------
extern "C" void kernel_launch(void* const* d_in, const int* in_sizes, int n_in,
                              void* d_out, int out_size)
{
    const float* z        = (const float*)d_in[0];
    const float* node_emb = (const float*)d_in[1];
    const int*   graph_id = (const int*)  d_in[2];
    const int*   src      = (const int*)  d_in[3];
    const int*   dst      = (const int*)  d_in[4];
    const float* lp_w  = (const float*)d_in[5];
    const float* lp_b  = (const float*)d_in[6];
    const float* nep_w = (const float*)d_in[7];
    const float* nep_b = (const float*)d_in[8];
    const float* nd1_w = (const float*)d_in[9];
    const float* nd1_b = (const float*)d_in[10];
    const float* nd2_w = (const float*)d_in[11];
    const float* nd2_b = (const float*)d_in[12];
    const float* ed1_w = (const float*)d_in[13];
    const float* ed1_b = (const float*)d_in[14];
    const float* ed2_w = (const float*)d_in[15];
    const float* ed2_b = (const float*)d_in[16];
    const float* en1_w = (const float*)d_in[17];
    const float* en1_b = (const float*)d_in[18];
    const float* en2_w = (const float*)d_in[19];
    const float* en2_b = (const float*)d_in[20];
    const float* st1_w = (const float*)d_in[21];
    const float* st1_b = (const float*)d_in[22];
    const float* st2_w = (const float*)d_in[23];
    const float* st2_b = (const float*)d_in[24];

    const int B = in_sizes[0] / 32;
    const int N = in_sizes[1] / 128;
    const int E = in_sizes[3];

    float* out        = (float*)d_out;
    float* out_node   = out;
    float* out_edge   = out + (size_t)N * 4;
    float* out_energy = out + (size_t)N * 4 + (size_t)E * 3;
    float* out_stress = out_energy + (size_t)B * 2;

    cudaFuncSetAttribute(node_mma_kernel, cudaFuncAttributeMaxDynamicSharedMemorySize,
                         NODE_SMEM_BYTES);

    wconv_kernel<<<64, 256>>>(nep_w, nd1_w);

    prep_kernel<<<B, 128>>>(z, lp_w, lp_b, nd1_w, ed1_w,
                            en1_w, en1_b, en2_w, en2_b,
                            st1_w, st1_b, st2_w, st2_b,
                            out_energy, out_stress);

    edge_table_kernel<<<B, 256>>>(ed1_b, ed2_w, ed2_b);

    const int ntiles = (N + 127) / 128;
    const int grid = ntiles < 148 ? ntiles : 148;
    node_mma_kernel<<<grid, 256, NODE_SMEM_BYTES>>>(node_emb, graph_id,
                                                    nep_b, nd1_b, nd2_w, nd2_b,
                                                    out_node, N, ntiles);

    const int eth = (E + 3) / 4;
    edge_gather_kernel<<<(eth + 255) / 256, 256>>>(src, dst, graph_id, out_edge, E);
}

// round 4
// speedup vs baseline: 1.8063x; 1.0870x over previous
#include <cuda_runtime.h>
#include <cuda_bf16.h>
#include <cstdint>

// ---------------------------------------------------------------------------
// CrystalDecoder on GB300 (sm_103a via compute_103 PTX -> HMMA mma.sync only)
// Node path: 16-warp warp-pair bf16 hi/lo compensated mma.sync GEMM.
// Edge path: algebraic collapse to 256x256 lookup table + gather.
// ---------------------------------------------------------------------------

#define MAXB 256

__device__ float  g_zb[MAXB * 64];      // z_proj @ nd1_w
__device__ float  g_As[MAXB * 64];
__device__ float  g_Bd[MAXB * 64];
__device__ float4 g_table[MAXB * MAXB];

// pre-converted transposed weights, bf16 hi/lo: W1^T [128 n][128 k], W2^T [64 n][128 k]
__device__ uint16_t g_w1thi[128 * 128];
__device__ uint16_t g_w1tlo[128 * 128];
__device__ uint16_t g_w2thi[64 * 128];
__device__ uint16_t g_w2tlo[64 * 128];

// u32 stride 68: (68*g + 8s + tg) mod 32 = (4g+tg) -> perfect bank permutation
#define XS 68
#define ZS 68

#define MMA16816(c, a, b0, b1) \
    asm volatile("mma.sync.aligned.m16n8k16.row.col.f32.bf16.bf16.f32 " \
        "{%0,%1,%2,%3}, {%4,%5,%6,%7}, {%8,%9}, {%0,%1,%2,%3};" \
        : "+f"((c)[0]), "+f"((c)[1]), "+f"((c)[2]), "+f"((c)[3]) \
        : "r"((a)[0]), "r"((a)[1]), "r"((a)[2]), "r"((a)[3]), "r"(b0), "r"(b1))

__device__ __forceinline__ uint32_t pkbf(float a, float b) {
    __nv_bfloat162 t = __floats2bfloat162_rn(a, b);
    return *(uint32_t*)&t;
}

// ---------------------------------------------------------------------------
__global__ void wconv_kernel(const float* __restrict__ w1, const float* __restrict__ w2)
{
    int i = blockIdx.x * blockDim.x + threadIdx.x;
    if (i < 128 * 128) {
        int k = i >> 7, n = i & 127;
        float v = w1[k * 128 + n];
        __nv_bfloat16 h = __float2bfloat16(v);
        __nv_bfloat16 l = __float2bfloat16(v - __bfloat162float(h));
        g_w1thi[n * 128 + k] = *(uint16_t*)&h;
        g_w1tlo[n * 128 + k] = *(uint16_t*)&l;
    }
    if (i < 64 * 128) {
        int k = i >> 6, n = i & 63;
        float v = w2[k * 64 + n];
        __nv_bfloat16 h = __float2bfloat16(v);
        __nv_bfloat16 l = __float2bfloat16(v - __bfloat162float(h));
        g_w2thi[n * 128 + k] = *(uint16_t*)&h;
        g_w2tlo[n * 128 + k] = *(uint16_t*)&l;
    }
}

// ---------------------------------------------------------------------------
// Persistent node kernel: 512 threads, 16 warps = 8 pairs.
// Pair p -> rows 16p..16p+15. half h=w&1: L1 n-tiles [8h,8h+8); L2 k-split.
// ---------------------------------------------------------------------------
#define NODE_SMEM_U32 (2*128*XS + 2*64*XS + 2*128*XS + 128*ZS + 128 + 64 + 256 + 128)
#define NODE_SMEM_BYTES (NODE_SMEM_U32 * 4)

__global__ void __launch_bounds__(512, 1)
node_mma_kernel(const float* __restrict__ node_emb, const int* __restrict__ graph_id,
                const float* __restrict__ b1, const float* __restrict__ b2,
                const float* __restrict__ w3, const float* __restrict__ b3,
                float* __restrict__ out_node, int N, int ntiles)
{
    extern __shared__ uint32_t su[];
    uint32_t* sW1h = su;                        // [128][XS]
    uint32_t* sW1l = sW1h + 128 * XS;
    uint32_t* sW2h = sW1l + 128 * XS;           // [64][XS]
    uint32_t* sW2l = sW2h + 64 * XS;
    uint32_t* sXh  = sW2l + 64 * XS;            // [128][XS]; reused as merge buffer
    uint32_t* sXl  = sXh + 128 * XS;
    float*    szb  = (float*)(sXl + 128 * XS);  // [128][ZS]
    float*    sB1  = szb + 128 * ZS;            // [128]
    float*    sB2  = sB1 + 128;                 // [64]
    float*    sW3  = sB2 + 64;                  // [64][4]
    int*      sG   = (int*)(sW3 + 256);         // [128]
    float*    smrg = (float*)sXh;               // [8 pairs][32 idx][32 lane]

    const int tid  = threadIdx.x;
    const int lane = tid & 31;
    const int w    = tid >> 5;       // 0..15
    const int p    = w >> 1;         // pair 0..7
    const int h    = w & 1;          // half
    const int g    = lane >> 2;
    const int tg   = lane & 3;
    const int r0   = p * 16;

    // ---- one-time staging ----
    for (int i = tid; i < 128 * 64; i += 512) {
        int n = i >> 6, kp = i & 63;
        sW1h[n * XS + kp] = ((const uint32_t*)g_w1thi)[i];
        sW1l[n * XS + kp] = ((const uint32_t*)g_w1tlo)[i];
    }
    for (int i = tid; i < 64 * 64; i += 512) {
        int n = i >> 6, kp = i & 63;
        sW2h[n * XS + kp] = ((const uint32_t*)g_w2thi)[i];
        sW2l[n * XS + kp] = ((const uint32_t*)g_w2tlo)[i];
    }
    if (tid < 128) sB1[tid] = b1[tid];
    else if (tid < 192) sB2[tid - 128] = b2[tid - 128];
    else if (tid >= 256 && tid < 320) ((float4*)sW3)[tid - 256] = ((const float4*)w3)[tid - 256];
    const float b30 = b3[0], b31 = b3[1], b32 = b3[2], b33 = b3[3];
    __syncthreads();

    for (int tile = blockIdx.x; tile < ntiles; tile += gridDim.x) {
        const int base = tile * 128;

        // ---- stage gid + X (bf16 hi/lo split) ----
        if (tid < 128) {
            int n = base + tid;
            sG[tid] = (n < N) ? graph_id[n] : 0;
        }
        #pragma unroll
        for (int it = 0; it < 8; it++) {
            int idx = it * 512 + tid;        // 0..4095
            int n = idx >> 5;                // row 0..127
            int q = idx & 31;                // float4 index
            int gn = base + n;
            float4 v = (gn < N) ? ((const float4*)(node_emb + (size_t)gn * 128))[q]
                                : make_float4(0.f, 0.f, 0.f, 0.f);
            float hx = __bfloat162float(__float2bfloat16(v.x));
            float hy = __bfloat162float(__float2bfloat16(v.y));
            float hz = __bfloat162float(__float2bfloat16(v.z));
            float hw = __bfloat162float(__float2bfloat16(v.w));
            *(uint2*)&sXh[n * XS + 2 * q] = make_uint2(pkbf(hx, hy), pkbf(hz, hw));
            *(uint2*)&sXl[n * XS + 2 * q] = make_uint2(pkbf(v.x - hx, v.y - hy),
                                                       pkbf(v.z - hz, v.w - hw));
        }
        __syncthreads();

        // ---- stage zb = g_zb[gid] + b2 ----
        #pragma unroll
        for (int it = 0; it < 4; it++) {
            int i = it * 512 + tid;          // 0..2047
            int row = i >> 4;
            int c4  = i & 15;
            int gid = sG[row];
            float4 zv = ((const float4*)(g_zb + gid * 64))[c4];
            float4 bb = ((const float4*)sB2)[c4];
            ((float4*)szb)[row * (ZS / 4) + c4] =
                make_float4(zv.x + bb.x, zv.y + bb.y, zv.z + bb.z, zv.w + bb.w);
        }
        __syncthreads();

        // ---- Layer 1: 8 n-tiles (global nt = 8h+j), all 8 k-steps ----
        float acc[8][4];
        #pragma unroll
        for (int j = 0; j < 8; j++)
            #pragma unroll
            for (int q = 0; q < 4; q++) acc[j][q] = 0.f;

        const uint32_t* xh0 = &sXh[(r0 + g) * XS];
        const uint32_t* xh1 = &sXh[(r0 + g + 8) * XS];
        const uint32_t* xl0 = &sXl[(r0 + g) * XS];
        const uint32_t* xl1 = &sXl[(r0 + g + 8) * XS];

        #pragma unroll
        for (int s = 0; s < 8; s++) {
            const int o = s * 8 + tg;
            uint32_t aH[4] = { xh0[o], xh1[o], xh0[o + 4], xh1[o + 4] };
            uint32_t aL[4] = { xl0[o], xl1[o], xl0[o + 4], xl1[o + 4] };
            #pragma unroll
            for (int j = 0; j < 8; j++) {
                const int nrow = ((8 * h + j) * 8 + g) * XS;
                uint32_t bh0 = sW1h[nrow + o], bh1 = sW1h[nrow + o + 4];
                uint32_t bl0 = sW1l[nrow + o], bl1 = sW1l[nrow + o + 4];
                MMA16816(acc[j], aH, bh0, bh1);
                MMA16816(acc[j], aH, bl0, bl1);
                MMA16816(acc[j], aL, bh0, bh1);
            }
        }

        // ---- epilogue 1 (registers): bias+relu, bf16 hi/lo -> A2 frags ----
        // local s2 slot covers global k-step 4h+s2
        uint32_t a2h[4][4], a2l[4][4];
        #pragma unroll
        for (int s2 = 0; s2 < 4; s2++) {
            int cA = (4 * h + s2) * 16 + tg * 2;
            int cB = cA + 8;
            float bA0 = sB1[cA], bA1 = sB1[cA + 1];
            float bB0 = sB1[cB], bB1 = sB1[cB + 1];
            {
                float x0 = fmaxf(acc[2 * s2][0] + bA0, 0.f);
                float x1 = fmaxf(acc[2 * s2][1] + bA1, 0.f);
                float h0 = __bfloat162float(__float2bfloat16(x0));
                float h1 = __bfloat162float(__float2bfloat16(x1));
                a2h[s2][0] = pkbf(h0, h1);
                a2l[s2][0] = pkbf(x0 - h0, x1 - h1);
            }
            {
                float x0 = fmaxf(acc[2 * s2][2] + bA0, 0.f);
                float x1 = fmaxf(acc[2 * s2][3] + bA1, 0.f);
                float h0 = __bfloat162float(__float2bfloat16(x0));
                float h1 = __bfloat162float(__float2bfloat16(x1));
                a2h[s2][1] = pkbf(h0, h1);
                a2l[s2][1] = pkbf(x0 - h0, x1 - h1);
            }
            {
                float x0 = fmaxf(acc[2 * s2 + 1][0] + bB0, 0.f);
                float x1 = fmaxf(acc[2 * s2 + 1][1] + bB1, 0.f);
                float h0 = __bfloat162float(__float2bfloat16(x0));
                float h1 = __bfloat162float(__float2bfloat16(x1));
                a2h[s2][2] = pkbf(h0, h1);
                a2l[s2][2] = pkbf(x0 - h0, x1 - h1);
            }
            {
                float x0 = fmaxf(acc[2 * s2 + 1][2] + bB0, 0.f);
                float x1 = fmaxf(acc[2 * s2 + 1][3] + bB1, 0.f);
                float h0 = __bfloat162float(__float2bfloat16(x0));
                float h1 = __bfloat162float(__float2bfloat16(x1));
                a2h[s2][3] = pkbf(h0, h1);
                a2l[s2][3] = pkbf(x0 - h0, x1 - h1);
            }
        }
        __syncthreads();   // X buffer dead -> merge region reusable

        // ---- Layer 2: all 8 n-tiles, local k-half (4 steps) -> partial ----
        float acc2[8][4];
        #pragma unroll
        for (int j = 0; j < 8; j++)
            #pragma unroll
            for (int q = 0; q < 4; q++) acc2[j][q] = 0.f;

        #pragma unroll
        for (int s = 0; s < 4; s++) {
            const int o = (4 * h + s) * 8 + tg;
            #pragma unroll
            for (int j = 0; j < 8; j++) {
                const int nrow = (j * 8 + g) * XS;
                uint32_t bh0 = sW2h[nrow + o], bh1 = sW2h[nrow + o + 4];
                uint32_t bl0 = sW2l[nrow + o], bl1 = sW2l[nrow + o + 4];
                MMA16816(acc2[j], a2h[s], bh0, bh1);
                MMA16816(acc2[j], a2h[s], bl0, bl1);
                MMA16816(acc2[j], a2l[s], bh0, bh1);
            }
        }

        // ---- pair merge: even stores partial; odd merges + epilogue 2 ----
        float* mb = smrg + p * 1024;
        if (h == 0) {
            #pragma unroll
            for (int j = 0; j < 8; j++)
                #pragma unroll
                for (int q = 0; q < 4; q++)
                    mb[(j * 4 + q) * 32 + lane] = acc2[j][q];
        }
        asm volatile("bar.sync %0, %1;" :: "r"(p + 1), "r"(64) : "memory");
        if (h == 1) {
            #pragma unroll
            for (int j = 0; j < 8; j++)
                #pragma unroll
                for (int q = 0; q < 4; q++)
                    acc2[j][q] += mb[(j * 4 + q) * 32 + lane];

            const int rA = r0 + g;
            const int rB = rA + 8;
            float oA0 = 0.f, oA1 = 0.f, oA2 = 0.f, oA3 = 0.f;
            float oB0 = 0.f, oB1 = 0.f, oB2 = 0.f, oB3 = 0.f;
            #pragma unroll
            for (int nt = 0; nt < 8; nt++) {
                int c0 = nt * 8 + tg * 2;
                int c1 = c0 + 1;
                float hA0 = fmaxf(acc2[nt][0] + szb[rA * ZS + c0], 0.f);
                float hA1 = fmaxf(acc2[nt][1] + szb[rA * ZS + c1], 0.f);
                float hB0 = fmaxf(acc2[nt][2] + szb[rB * ZS + c0], 0.f);
                float hB1 = fmaxf(acc2[nt][3] + szb[rB * ZS + c1], 0.f);
                float4 w0 = *(const float4*)&sW3[c0 * 4];
                float4 w1 = *(const float4*)&sW3[c1 * 4];
                oA0 = fmaf(hA0, w0.x, fmaf(hA1, w1.x, oA0));
                oA1 = fmaf(hA0, w0.y, fmaf(hA1, w1.y, oA1));
                oA2 = fmaf(hA0, w0.z, fmaf(hA1, w1.z, oA2));
                oA3 = fmaf(hA0, w0.w, fmaf(hA1, w1.w, oA3));
                oB0 = fmaf(hB0, w0.x, fmaf(hB1, w1.x, oB0));
                oB1 = fmaf(hB0, w0.y, fmaf(hB1, w1.y, oB1));
                oB2 = fmaf(hB0, w0.z, fmaf(hB1, w1.z, oB2));
                oB3 = fmaf(hB0, w0.w, fmaf(hB1, w1.w, oB3));
            }
            #pragma unroll
            for (int d = 1; d <= 2; d <<= 1) {
                oA0 += __shfl_xor_sync(0xFFFFFFFF, oA0, d);
                oA1 += __shfl_xor_sync(0xFFFFFFFF, oA1, d);
                oA2 += __shfl_xor_sync(0xFFFFFFFF, oA2, d);
                oA3 += __shfl_xor_sync(0xFFFFFFFF, oA3, d);
                oB0 += __shfl_xor_sync(0xFFFFFFFF, oB0, d);
                oB1 += __shfl_xor_sync(0xFFFFFFFF, oB1, d);
                oB2 += __shfl_xor_sync(0xFFFFFFFF, oB2, d);
                oB3 += __shfl_xor_sync(0xFFFFFFFF, oB3, d);
            }
            if (tg == 0) {
                int nA = base + rA;
                if (nA < N)
                    *(float4*)&out_node[(size_t)nA * 4] =
                        make_float4(oA0 + b30, oA1 + b31, oA2 + b32, oA3 + b33);
                int nB = base + rB;
                if (nB < N)
                    *(float4*)&out_node[(size_t)nB * 4] =
                        make_float4(oB0 + b30, oB1 + b31, oB2 + b32, oB3 + b33);
            }
        }
        __syncthreads();   // protect sXh(merge)/szb/sG before next staging
    }
}

// ---------------------------------------------------------------------------
// Per-graph prep (unchanged)
// ---------------------------------------------------------------------------
__global__ void prep_kernel(const float* __restrict__ z,
                            const float* __restrict__ lp_w, const float* __restrict__ lp_b,
                            const float* __restrict__ nd1_w,
                            const float* __restrict__ ed1_w,
                            const float* __restrict__ en1_w, const float* __restrict__ en1_b,
                            const float* __restrict__ en2_w, const float* __restrict__ en2_b,
                            const float* __restrict__ st1_w, const float* __restrict__ st1_b,
                            const float* __restrict__ st2_w, const float* __restrict__ st2_b,
                            float* __restrict__ out_energy, float* __restrict__ out_stress)
{
    const int b = blockIdx.x;
    const int t = threadIdx.x;
    __shared__ float zrow[32];
    __shared__ float zp[128];
    __shared__ float eh[64], sh[64];

    if (t < 32) zrow[t] = z[b * 32 + t];
    __syncthreads();
    {
        float acc = lp_b[t];
        #pragma unroll
        for (int k = 0; k < 32; k++) acc = fmaf(zrow[k], lp_w[k * 128 + t], acc);
        zp[t] = fmaxf(acc, 0.f);
    }
    if (t < 64) {
        float a1 = en1_b[t], a2 = st1_b[t];
        #pragma unroll
        for (int k = 0; k < 32; k++) {
            float zv = zrow[k];
            a1 = fmaf(zv, en1_w[k * 64 + t], a1);
            a2 = fmaf(zv, st1_w[k * 64 + t], a2);
        }
        eh[t] = fmaxf(a1, 0.f);
        sh[t] = fmaxf(a2, 0.f);
    }
    __syncthreads();
    if (t < 64) {
        float as = 0.f, bd = 0.f, zb = 0.f;
        #pragma unroll 4
        for (int k = 0; k < 128; k++) {
            float zv = zp[k];
            as = fmaf(zv, ed1_w[k * 64 + t], as);
            bd = fmaf(zv, ed1_w[(128 + k) * 64 + t], bd);
            zb = fmaf(zv, nd1_w[k * 64 + t], zb);
        }
        g_As[b * 64 + t] = as;
        g_Bd[b * 64 + t] = bd;
        g_zb[b * 64 + t] = zb;
    }
    if (t < 2) {
        float a = en2_b[t];
        #pragma unroll 8
        for (int k = 0; k < 64; k++) a = fmaf(eh[k], en2_w[k * 2 + t], a);
        out_energy[b * 2 + t] = a;
    }
    if (t >= 16 && t < 25) {
        int j = t - 16;
        float a = st2_b[j];
        #pragma unroll 8
        for (int k = 0; k < 64; k++) a = fmaf(sh[k], st2_w[k * 9 + j], a);
        out_stress[b * 9 + j] = a;
    }
}

// ---------------------------------------------------------------------------
// Edge table (unchanged)
// ---------------------------------------------------------------------------
__global__ void edge_table_kernel(const float* __restrict__ ed1_b,
                                  const float* __restrict__ ed2_w,
                                  const float* __restrict__ ed2_b)
{
    const int gs = blockIdx.x;
    const int gd = threadIdx.x;
    __shared__ float sAs[64], sb1[64], sw2[64 * 3], sb2[3];
    const int t = threadIdx.x;
    if (t < 64) { sAs[t] = g_As[gs * 64 + t]; sb1[t] = ed1_b[t]; }
    if (t >= 64 && t < 64 + 192) sw2[t - 64] = ed2_w[t - 64];
    if (t < 3) sb2[t] = ed2_b[t];
    __syncthreads();

    float o0 = sb2[0], o1 = sb2[1], o2 = sb2[2];
    const float4* bd4 = (const float4*)(&g_Bd[gd * 64]);
    #pragma unroll
    for (int k4 = 0; k4 < 16; k4++) {
        float4 bv = bd4[k4];
        int k = k4 * 4;
        float h;
        h = fmaxf(sAs[k + 0] + bv.x + sb1[k + 0], 0.f);
        o0 = fmaf(h, sw2[(k + 0) * 3 + 0], o0); o1 = fmaf(h, sw2[(k + 0) * 3 + 1], o1); o2 = fmaf(h, sw2[(k + 0) * 3 + 2], o2);
        h = fmaxf(sAs[k + 1] + bv.y + sb1[k + 1], 0.f);
        o0 = fmaf(h, sw2[(k + 1) * 3 + 0], o0); o1 = fmaf(h, sw2[(k + 1) * 3 + 1], o1); o2 = fmaf(h, sw2[(k + 1) * 3 + 2], o2);
        h = fmaxf(sAs[k + 2] + bv.z + sb1[k + 2], 0.f);
        o0 = fmaf(h, sw2[(k + 2) * 3 + 0], o0); o1 = fmaf(h, sw2[(k + 2) * 3 + 1], o1); o2 = fmaf(h, sw2[(k + 2) * 3 + 2], o2);
        h = fmaxf(sAs[k + 3] + bv.w + sb1[k + 3], 0.f);
        o0 = fmaf(h, sw2[(k + 3) * 3 + 0], o0); o1 = fmaf(h, sw2[(k + 3) * 3 + 1], o1); o2 = fmaf(h, sw2[(k + 3) * 3 + 2], o2);
    }
    g_table[gs * MAXB + gd] = make_float4(o0, o1, o2, 0.f);
}

// ---------------------------------------------------------------------------
// Edge gather: 8 edges/thread, batched independent loads (MLP 16)
// ---------------------------------------------------------------------------
__global__ void edge_gather_kernel(const int* __restrict__ src, const int* __restrict__ dst,
                                   const int* __restrict__ graph_id,
                                   float* __restrict__ out_edge, int E)
{
    int e = (blockIdx.x * blockDim.x + threadIdx.x) * 8;
    if (e >= E) return;
    if (e + 8 <= E) {
        int4 s0 = *(const int4*)(src + e);
        int4 s1 = *(const int4*)(src + e + 4);
        int4 d0 = *(const int4*)(dst + e);
        int4 d1 = *(const int4*)(dst + e + 4);
        int gs0 = graph_id[s0.x], gs1 = graph_id[s0.y], gs2 = graph_id[s0.z], gs3 = graph_id[s0.w];
        int gs4 = graph_id[s1.x], gs5 = graph_id[s1.y], gs6 = graph_id[s1.z], gs7 = graph_id[s1.w];
        int gd0 = graph_id[d0.x], gd1 = graph_id[d0.y], gd2 = graph_id[d0.z], gd3 = graph_id[d0.w];
        int gd4 = graph_id[d1.x], gd5 = graph_id[d1.y], gd6 = graph_id[d1.z], gd7 = graph_id[d1.w];
        float4 t0 = g_table[gs0 * MAXB + gd0];
        float4 t1 = g_table[gs1 * MAXB + gd1];
        float4 t2 = g_table[gs2 * MAXB + gd2];
        float4 t3 = g_table[gs3 * MAXB + gd3];
        float4 t4 = g_table[gs4 * MAXB + gd4];
        float4 t5 = g_table[gs5 * MAXB + gd5];
        float4 t6 = g_table[gs6 * MAXB + gd6];
        float4 t7 = g_table[gs7 * MAXB + gd7];
        float* o = out_edge + (size_t)e * 3;
        ((float4*)o)[0] = make_float4(t0.x, t0.y, t0.z, t1.x);
        ((float4*)o)[1] = make_float4(t1.y, t1.z, t2.x, t2.y);
        ((float4*)o)[2] = make_float4(t2.z, t3.x, t3.y, t3.z);
        ((float4*)o)[3] = make_float4(t4.x, t4.y, t4.z, t5.x);
        ((float4*)o)[4] = make_float4(t5.y, t5.z, t6.x, t6.y);
        ((float4*)o)[5] = make_float4(t6.z, t7.x, t7.y, t7.z);
    } else {
        for (int q = e; q < E; q++) {
            float4 t = g_table[graph_id[src[q]] * MAXB + graph_id[dst[q]]];
            out_edge[(size_t)q * 3 + 0] = t.x;
            out_edge[(size_t)q * 3 + 1] = t.y;
            out_edge[(size_t)q * 3 + 2] = t.z;
        }
    }
}

// ---------------------------------------------------------------------------
extern "C" void kernel_launch(void* const* d_in, const int* in_sizes, int n_in,
                              void* d_out, int out_size)
{
    const float* z        = (const float*)d_in[0];
    const float* node_emb = (const float*)d_in[1];
    const int*   graph_id = (const int*)  d_in[2];
    const int*   src      = (const int*)  d_in[3];
    const int*   dst      = (const int*)  d_in[4];
    const float* lp_w  = (const float*)d_in[5];
    const float* lp_b  = (const float*)d_in[6];
    const float* nep_w = (const float*)d_in[7];
    const float* nep_b = (const float*)d_in[8];
    const float* nd1_w = (const float*)d_in[9];
    const float* nd1_b = (const float*)d_in[10];
    const float* nd2_w = (const float*)d_in[11];
    const float* nd2_b = (const float*)d_in[12];
    const float* ed1_w = (const float*)d_in[13];
    const float* ed1_b = (const float*)d_in[14];
    const float* ed2_w = (const float*)d_in[15];
    const float* ed2_b = (const float*)d_in[16];
    const float* en1_w = (const float*)d_in[17];
    const float* en1_b = (const float*)d_in[18];
    const float* en2_w = (const float*)d_in[19];
    const float* en2_b = (const float*)d_in[20];
    const float* st1_w = (const float*)d_in[21];
    const float* st1_b = (const float*)d_in[22];
    const float* st2_w = (const float*)d_in[23];
    const float* st2_b = (const float*)d_in[24];

    const int B = in_sizes[0] / 32;
    const int N = in_sizes[1] / 128;
    const int E = in_sizes[3];

    float* out        = (float*)d_out;
    float* out_node   = out;
    float* out_edge   = out + (size_t)N * 4;
    float* out_energy = out + (size_t)N * 4 + (size_t)E * 3;
    float* out_stress = out_energy + (size_t)B * 2;

    cudaFuncSetAttribute(node_mma_kernel, cudaFuncAttributeMaxDynamicSharedMemorySize,
                         NODE_SMEM_BYTES);

    wconv_kernel<<<64, 256>>>(nep_w, nd1_w);

    prep_kernel<<<B, 128>>>(z, lp_w, lp_b, nd1_w, ed1_w,
                            en1_w, en1_b, en2_w, en2_b,
                            st1_w, st1_b, st2_w, st2_b,
                            out_energy, out_stress);

    edge_table_kernel<<<B, 256>>>(ed1_b, ed2_w, ed2_b);

    const int ntiles = (N + 127) / 128;
    const int grid = ntiles < 148 ? ntiles : 148;
    node_mma_kernel<<<grid, 512, NODE_SMEM_BYTES>>>(node_emb, graph_id,
                                                    nep_b, nd1_b, nd2_w, nd2_b,
                                                    out_node, N, ntiles);

    const int eth = (E + 7) / 8;
    edge_gather_kernel<<<(eth + 255) / 256, 256>>>(src, dst, graph_id, out_edge, E);
}

// round 5
// speedup vs baseline: 2.0398x; 1.1293x over previous
#include <cuda_runtime.h>
#include <cuda_bf16.h>
#include <cstdint>

// ---------------------------------------------------------------------------
// CrystalDecoder on GB300 (sm_103a via compute_103 PTX -> HMMA mma.sync only)
// Node path: 16-warp pair-autonomous bf16 hi/lo compensated mma.sync GEMM
//            with cross-tile register prefetch of X.
// Edge path: algebraic collapse to 256x256 lookup table + gather.
// ---------------------------------------------------------------------------

#define MAXB 256

__device__ float  g_zb[MAXB * 64];      // z_proj @ nd1_w + nd1_b  (b2 folded)
__device__ float  g_As[MAXB * 64];
__device__ float  g_Bd[MAXB * 64];
__device__ float4 g_table[MAXB * MAXB];

// pre-converted transposed weights, bf16 hi/lo: W1^T [128 n][128 k], W2^T [64 n][128 k]
__device__ uint16_t g_w1thi[128 * 128];
__device__ uint16_t g_w1tlo[128 * 128];
__device__ uint16_t g_w2thi[64 * 128];
__device__ uint16_t g_w2tlo[64 * 128];

// u32 stride 68: (68*g + 8s + tg) mod 32 = (4g+tg) -> perfect bank permutation
#define XS 68
#define ZS 68

#define MMA16816(c, a, b0, b1) \
    asm volatile("mma.sync.aligned.m16n8k16.row.col.f32.bf16.bf16.f32 " \
        "{%0,%1,%2,%3}, {%4,%5,%6,%7}, {%8,%9}, {%0,%1,%2,%3};" \
        : "+f"((c)[0]), "+f"((c)[1]), "+f"((c)[2]), "+f"((c)[3]) \
        : "r"((a)[0]), "r"((a)[1]), "r"((a)[2]), "r"((a)[3]), "r"(b0), "r"(b1))

#define PAIR_BAR(id) asm volatile("bar.sync %0, 64;" :: "r"(id) : "memory")

__device__ __forceinline__ uint32_t pkbf(float a, float b) {
    __nv_bfloat162 t = __floats2bfloat162_rn(a, b);
    return *(uint32_t*)&t;
}

// ---------------------------------------------------------------------------
__global__ void wconv_kernel(const float* __restrict__ w1, const float* __restrict__ w2)
{
    int i = blockIdx.x * blockDim.x + threadIdx.x;
    if (i < 128 * 128) {
        int k = i >> 7, n = i & 127;
        float v = w1[k * 128 + n];
        __nv_bfloat16 h = __float2bfloat16(v);
        __nv_bfloat16 l = __float2bfloat16(v - __bfloat162float(h));
        g_w1thi[n * 128 + k] = *(uint16_t*)&h;
        g_w1tlo[n * 128 + k] = *(uint16_t*)&l;
    }
    if (i < 64 * 128) {
        int k = i >> 6, n = i & 63;
        float v = w2[k * 64 + n];
        __nv_bfloat16 h = __float2bfloat16(v);
        __nv_bfloat16 l = __float2bfloat16(v - __bfloat162float(h));
        g_w2thi[n * 128 + k] = *(uint16_t*)&h;
        g_w2tlo[n * 128 + k] = *(uint16_t*)&l;
    }
}

// ---------------------------------------------------------------------------
// Persistent node kernel: 512 threads, 16 warps = 8 autonomous pairs.
// Pair p -> rows 16p..16p+15. half h: L1 n-half; L2 k-half + pair merge.
// ---------------------------------------------------------------------------
#define NODE_SMEM_U32 (2*128*XS + 2*64*XS + 2*128*XS + 128*ZS + 128 + 256)
#define NODE_SMEM_BYTES (NODE_SMEM_U32 * 4)

__global__ void __launch_bounds__(512, 1)
node_mma_kernel(const float* __restrict__ node_emb, const int* __restrict__ graph_id,
                const float* __restrict__ b1,
                const float* __restrict__ w3, const float* __restrict__ b3,
                float* __restrict__ out_node, int N, int ntiles)
{
    extern __shared__ uint32_t su[];
    uint32_t* sW1h = su;                        // [128][XS]
    uint32_t* sW1l = sW1h + 128 * XS;
    uint32_t* sW2h = sW1l + 128 * XS;           // [64][XS]
    uint32_t* sW2l = sW2h + 64 * XS;
    uint32_t* sXh  = sW2l + 64 * XS;            // [128][XS]
    uint32_t* sXl  = sXh + 128 * XS;            // [128][XS]; pair merge aliases own rows
    float*    szb  = (float*)(sXl + 128 * XS);  // [128][ZS]  (zb + nd1_b, pre-folded)
    float*    sB1  = szb + 128 * ZS;            // [128]
    float*    sW3  = sB1 + 128;                 // [64][4]

    const int tid  = threadIdx.x;
    const int lane = tid & 31;
    const int w    = tid >> 5;       // 0..15
    const int p    = w >> 1;         // pair 0..7
    const int h    = w & 1;          // half
    const int g    = lane >> 2;
    const int tg   = lane & 3;
    const int r0   = p * 16;
    const int u    = tid & 63;       // thread within pair
    const int barid = p + 1;
    float* mrg = (float*)(sXl + p * 1088);   // 1024 floats inside own pair rows

    // ---- one-time staging (block-wide) ----
    for (int i = tid; i < 128 * 64; i += 512) {
        int n = i >> 6, kp = i & 63;
        sW1h[n * XS + kp] = ((const uint32_t*)g_w1thi)[i];
        sW1l[n * XS + kp] = ((const uint32_t*)g_w1tlo)[i];
    }
    for (int i = tid; i < 64 * 64; i += 512) {
        int n = i >> 6, kp = i & 63;
        sW2h[n * XS + kp] = ((const uint32_t*)g_w2thi)[i];
        sW2l[n * XS + kp] = ((const uint32_t*)g_w2tlo)[i];
    }
    if (tid < 128) sB1[tid] = b1[tid];
    else if (tid >= 256 && tid < 320) ((float4*)sW3)[tid - 256] = ((const float4*)w3)[tid - 256];
    const float b30 = b3[0], b31 = b3[1], b32 = b3[2], b33 = b3[3];

    // ---- prologue: stage tile0 (pair-local rows only) ----
    int tile = blockIdx.x;
    if (tile < ntiles) {
        const int base = tile * 128;
        #pragma unroll
        for (int it = 0; it < 8; it++) {
            int idx = it * 64 + u;
            int row = r0 + (idx >> 5);
            int q   = idx & 31;
            int gn  = base + row;
            float4 v = (gn < N) ? ((const float4*)(node_emb + (size_t)gn * 128))[q]
                                : make_float4(0.f, 0.f, 0.f, 0.f);
            float hx = __bfloat162float(__float2bfloat16(v.x));
            float hy = __bfloat162float(__float2bfloat16(v.y));
            float hz = __bfloat162float(__float2bfloat16(v.z));
            float hw = __bfloat162float(__float2bfloat16(v.w));
            *(uint2*)&sXh[row * XS + 2 * q] = make_uint2(pkbf(hx, hy), pkbf(hz, hw));
            *(uint2*)&sXl[row * XS + 2 * q] = make_uint2(pkbf(v.x - hx, v.y - hy),
                                                         pkbf(v.z - hz, v.w - hw));
        }
        {
            int row = r0 + (u >> 2);
            int gn  = base + row;
            int gid = (gn < N) ? graph_id[gn] : 0;
            const float4* z4 = (const float4*)(g_zb + gid * 64);
            #pragma unroll
            for (int qq = 0; qq < 4; qq++) {
                int q = (u & 3) * 4 + qq;
                ((float4*)(szb + row * ZS))[q] = z4[q];
            }
        }
    }
    __syncthreads();   // only block-wide sync

    for (; tile < ntiles; tile += gridDim.x) {
        const int base = tile * 128;

        // ---- Layer 1: 8 n-tiles (global nt = 8h+j), all 8 k-steps ----
        float acc[8][4];
        #pragma unroll
        for (int j = 0; j < 8; j++)
            #pragma unroll
            for (int q = 0; q < 4; q++) acc[j][q] = 0.f;

        const uint32_t* xh0 = &sXh[(r0 + g) * XS];
        const uint32_t* xh1 = &sXh[(r0 + g + 8) * XS];
        const uint32_t* xl0 = &sXl[(r0 + g) * XS];
        const uint32_t* xl1 = &sXl[(r0 + g + 8) * XS];

        #pragma unroll
        for (int s = 0; s < 8; s++) {
            const int o = s * 8 + tg;
            uint32_t aH[4] = { xh0[o], xh1[o], xh0[o + 4], xh1[o + 4] };
            uint32_t aL[4] = { xl0[o], xl1[o], xl0[o + 4], xl1[o + 4] };
            #pragma unroll
            for (int j = 0; j < 8; j++) {
                const int nrow = ((8 * h + j) * 8 + g) * XS;
                uint32_t bh0 = sW1h[nrow + o], bh1 = sW1h[nrow + o + 4];
                uint32_t bl0 = sW1l[nrow + o], bl1 = sW1l[nrow + o + 4];
                MMA16816(acc[j], aH, bh0, bh1);
                MMA16816(acc[j], aH, bl0, bl1);
                MMA16816(acc[j], aL, bh0, bh1);
            }
        }
        PAIR_BAR(barid);   // barA: pair done reading its sX rows

        // ---- prefetch next tile's X into registers (latency hidden by L2) ----
        const int  ntile = tile + gridDim.x;
        const bool nv    = ntile < ntiles;
        float4 xp[8];
        if (nv) {
            const int nbase = ntile * 128;
            #pragma unroll
            for (int it = 0; it < 8; it++) {
                int idx = it * 64 + u;
                int row = r0 + (idx >> 5);
                int q   = idx & 31;
                int gn  = nbase + row;
                xp[it] = (gn < N) ? ((const float4*)(node_emb + (size_t)gn * 128))[q]
                                  : make_float4(0.f, 0.f, 0.f, 0.f);
            }
        }

        // ---- epilogue 1 (registers): bias+relu, bf16 hi/lo -> A2 frags ----
        uint32_t a2h[4][4], a2l[4][4];
        #pragma unroll
        for (int s2 = 0; s2 < 4; s2++) {
            int cA = (4 * h + s2) * 16 + tg * 2;
            int cB = cA + 8;
            float bA0 = sB1[cA], bA1 = sB1[cA + 1];
            float bB0 = sB1[cB], bB1 = sB1[cB + 1];
            {
                float x0 = fmaxf(acc[2 * s2][0] + bA0, 0.f);
                float x1 = fmaxf(acc[2 * s2][1] + bA1, 0.f);
                float h0 = __bfloat162float(__float2bfloat16(x0));
                float h1 = __bfloat162float(__float2bfloat16(x1));
                a2h[s2][0] = pkbf(h0, h1);
                a2l[s2][0] = pkbf(x0 - h0, x1 - h1);
            }
            {
                float x0 = fmaxf(acc[2 * s2][2] + bA0, 0.f);
                float x1 = fmaxf(acc[2 * s2][3] + bA1, 0.f);
                float h0 = __bfloat162float(__float2bfloat16(x0));
                float h1 = __bfloat162float(__float2bfloat16(x1));
                a2h[s2][1] = pkbf(h0, h1);
                a2l[s2][1] = pkbf(x0 - h0, x1 - h1);
            }
            {
                float x0 = fmaxf(acc[2 * s2 + 1][0] + bB0, 0.f);
                float x1 = fmaxf(acc[2 * s2 + 1][1] + bB1, 0.f);
                float h0 = __bfloat162float(__float2bfloat16(x0));
                float h1 = __bfloat162float(__float2bfloat16(x1));
                a2h[s2][2] = pkbf(h0, h1);
                a2l[s2][2] = pkbf(x0 - h0, x1 - h1);
            }
            {
                float x0 = fmaxf(acc[2 * s2 + 1][2] + bB0, 0.f);
                float x1 = fmaxf(acc[2 * s2 + 1][3] + bB1, 0.f);
                float h0 = __bfloat162float(__float2bfloat16(x0));
                float h1 = __bfloat162float(__float2bfloat16(x1));
                a2h[s2][3] = pkbf(h0, h1);
                a2l[s2][3] = pkbf(x0 - h0, x1 - h1);
            }
        }

        // ---- Layer 2: all 8 n-tiles, local k-half (4 steps) -> partial ----
        float acc2[8][4];
        #pragma unroll
        for (int j = 0; j < 8; j++)
            #pragma unroll
            for (int q = 0; q < 4; q++) acc2[j][q] = 0.f;

        #pragma unroll
        for (int s = 0; s < 4; s++) {
            const int o = (4 * h + s) * 8 + tg;
            #pragma unroll
            for (int j = 0; j < 8; j++) {
                const int nrow = (j * 8 + g) * XS;
                uint32_t bh0 = sW2h[nrow + o], bh1 = sW2h[nrow + o + 4];
                uint32_t bl0 = sW2l[nrow + o], bl1 = sW2l[nrow + o + 4];
                MMA16816(acc2[j], a2h[s], bh0, bh1);
                MMA16816(acc2[j], a2h[s], bl0, bl1);
                MMA16816(acc2[j], a2l[s], bh0, bh1);
            }
        }

        // ---- pair merge (buffer aliased onto own pair's dead sXl rows) ----
        if (h == 0) {
            #pragma unroll
            for (int j = 0; j < 8; j++)
                #pragma unroll
                for (int q = 0; q < 4; q++)
                    mrg[(j * 4 + q) * 32 + lane] = acc2[j][q];
        }
        PAIR_BAR(barid);   // barB

        if (h == 1) {
            #pragma unroll
            for (int j = 0; j < 8; j++)
                #pragma unroll
                for (int q = 0; q < 4; q++)
                    acc2[j][q] += mrg[(j * 4 + q) * 32 + lane];

            const int rA = r0 + g;
            const int rB = rA + 8;
            float oA0 = 0.f, oA1 = 0.f, oA2 = 0.f, oA3 = 0.f;
            float oB0 = 0.f, oB1 = 0.f, oB2 = 0.f, oB3 = 0.f;
            #pragma unroll
            for (int nt = 0; nt < 8; nt++) {
                int c0 = nt * 8 + tg * 2;
                int c1 = c0 + 1;
                float hA0 = fmaxf(acc2[nt][0] + szb[rA * ZS + c0], 0.f);
                float hA1 = fmaxf(acc2[nt][1] + szb[rA * ZS + c1], 0.f);
                float hB0 = fmaxf(acc2[nt][2] + szb[rB * ZS + c0], 0.f);
                float hB1 = fmaxf(acc2[nt][3] + szb[rB * ZS + c1], 0.f);
                float4 w0 = *(const float4*)&sW3[c0 * 4];
                float4 w1 = *(const float4*)&sW3[c1 * 4];
                oA0 = fmaf(hA0, w0.x, fmaf(hA1, w1.x, oA0));
                oA1 = fmaf(hA0, w0.y, fmaf(hA1, w1.y, oA1));
                oA2 = fmaf(hA0, w0.z, fmaf(hA1, w1.z, oA2));
                oA3 = fmaf(hA0, w0.w, fmaf(hA1, w1.w, oA3));
                oB0 = fmaf(hB0, w0.x, fmaf(hB1, w1.x, oB0));
                oB1 = fmaf(hB0, w0.y, fmaf(hB1, w1.y, oB1));
                oB2 = fmaf(hB0, w0.z, fmaf(hB1, w1.z, oB2));
                oB3 = fmaf(hB0, w0.w, fmaf(hB1, w1.w, oB3));
            }
            #pragma unroll
            for (int d = 1; d <= 2; d <<= 1) {
                oA0 += __shfl_xor_sync(0xFFFFFFFF, oA0, d);
                oA1 += __shfl_xor_sync(0xFFFFFFFF, oA1, d);
                oA2 += __shfl_xor_sync(0xFFFFFFFF, oA2, d);
                oA3 += __shfl_xor_sync(0xFFFFFFFF, oA3, d);
                oB0 += __shfl_xor_sync(0xFFFFFFFF, oB0, d);
                oB1 += __shfl_xor_sync(0xFFFFFFFF, oB1, d);
                oB2 += __shfl_xor_sync(0xFFFFFFFF, oB2, d);
                oB3 += __shfl_xor_sync(0xFFFFFFFF, oB3, d);
            }
            if (tg == 0) {
                int nA = base + rA;
                if (nA < N)
                    *(float4*)&out_node[(size_t)nA * 4] =
                        make_float4(oA0 + b30, oA1 + b31, oA2 + b32, oA3 + b33);
                int nB = base + rB;
                if (nB < N)
                    *(float4*)&out_node[(size_t)nB * 4] =
                        make_float4(oB0 + b30, oB1 + b31, oB2 + b32, oB3 + b33);
            }
        }

        // ---- write next X hi (sXh fully dead since barA) ----
        if (nv) {
            #pragma unroll
            for (int it = 0; it < 8; it++) {
                int idx = it * 64 + u;
                int row = r0 + (idx >> 5);
                int q   = idx & 31;
                float4 v = xp[it];
                float hx = __bfloat162float(__float2bfloat16(v.x));
                float hy = __bfloat162float(__float2bfloat16(v.y));
                float hz = __bfloat162float(__float2bfloat16(v.z));
                float hw = __bfloat162float(__float2bfloat16(v.w));
                *(uint2*)&sXh[row * XS + 2 * q] = make_uint2(pkbf(hx, hy), pkbf(hz, hw));
            }
        }
        PAIR_BAR(barid);   // barC: merge(sXl) + szb reads complete

        if (nv) {
            #pragma unroll
            for (int it = 0; it < 8; it++) {
                int idx = it * 64 + u;
                int row = r0 + (idx >> 5);
                int q   = idx & 31;
                float4 v = xp[it];
                float hx = __bfloat162float(__float2bfloat16(v.x));
                float hy = __bfloat162float(__float2bfloat16(v.y));
                float hz = __bfloat162float(__float2bfloat16(v.z));
                float hw = __bfloat162float(__float2bfloat16(v.w));
                *(uint2*)&sXl[row * XS + 2 * q] = make_uint2(pkbf(v.x - hx, v.y - hy),
                                                             pkbf(v.z - hz, v.w - hw));
            }
            // restage zb for next tile
            int row = r0 + (u >> 2);
            int gn  = ntile * 128 + row;
            int gid = (gn < N) ? graph_id[gn] : 0;
            const float4* z4 = (const float4*)(g_zb + gid * 64);
            #pragma unroll
            for (int qq = 0; qq < 4; qq++) {
                int q = (u & 3) * 4 + qq;
                ((float4*)(szb + row * ZS))[q] = z4[q];
            }
        }
        PAIR_BAR(barid);   // barD: staging done before next L1
    }
}

// ---------------------------------------------------------------------------
// Per-graph prep; nd1_b now folded into g_zb
// ---------------------------------------------------------------------------
__global__ void prep_kernel(const float* __restrict__ z,
                            const float* __restrict__ lp_w, const float* __restrict__ lp_b,
                            const float* __restrict__ nd1_w, const float* __restrict__ nd1_b,
                            const float* __restrict__ ed1_w,
                            const float* __restrict__ en1_w, const float* __restrict__ en1_b,
                            const float* __restrict__ en2_w, const float* __restrict__ en2_b,
                            const float* __restrict__ st1_w, const float* __restrict__ st1_b,
                            const float* __restrict__ st2_w, const float* __restrict__ st2_b,
                            float* __restrict__ out_energy, float* __restrict__ out_stress)
{
    const int b = blockIdx.x;
    const int t = threadIdx.x;
    __shared__ float zrow[32];
    __shared__ float zp[128];
    __shared__ float eh[64], sh[64];

    if (t < 32) zrow[t] = z[b * 32 + t];
    __syncthreads();
    {
        float acc = lp_b[t];
        #pragma unroll
        for (int k = 0; k < 32; k++) acc = fmaf(zrow[k], lp_w[k * 128 + t], acc);
        zp[t] = fmaxf(acc, 0.f);
    }
    if (t < 64) {
        float a1 = en1_b[t], a2 = st1_b[t];
        #pragma unroll
        for (int k = 0; k < 32; k++) {
            float zv = zrow[k];
            a1 = fmaf(zv, en1_w[k * 64 + t], a1);
            a2 = fmaf(zv, st1_w[k * 64 + t], a2);
        }
        eh[t] = fmaxf(a1, 0.f);
        sh[t] = fmaxf(a2, 0.f);
    }
    __syncthreads();
    if (t < 64) {
        float as = 0.f, bd = 0.f, zb = nd1_b[t];
        #pragma unroll 4
        for (int k = 0; k < 128; k++) {
            float zv = zp[k];
            as = fmaf(zv, ed1_w[k * 64 + t], as);
            bd = fmaf(zv, ed1_w[(128 + k) * 64 + t], bd);
            zb = fmaf(zv, nd1_w[k * 64 + t], zb);
        }
        g_As[b * 64 + t] = as;
        g_Bd[b * 64 + t] = bd;
        g_zb[b * 64 + t] = zb;
    }
    if (t < 2) {
        float a = en2_b[t];
        #pragma unroll 8
        for (int k = 0; k < 64; k++) a = fmaf(eh[k], en2_w[k * 2 + t], a);
        out_energy[b * 2 + t] = a;
    }
    if (t >= 16 && t < 25) {
        int j = t - 16;
        float a = st2_b[j];
        #pragma unroll 8
        for (int k = 0; k < 64; k++) a = fmaf(sh[k], st2_w[k * 9 + j], a);
        out_stress[b * 9 + j] = a;
    }
}

// ---------------------------------------------------------------------------
// Edge table (unchanged)
// ---------------------------------------------------------------------------
__global__ void edge_table_kernel(const float* __restrict__ ed1_b,
                                  const float* __restrict__ ed2_w,
                                  const float* __restrict__ ed2_b)
{
    const int gs = blockIdx.x;
    const int gd = threadIdx.x;
    __shared__ float sAs[64], sb1[64], sw2[64 * 3], sb2[3];
    const int t = threadIdx.x;
    if (t < 64) { sAs[t] = g_As[gs * 64 + t]; sb1[t] = ed1_b[t]; }
    if (t >= 64 && t < 64 + 192) sw2[t - 64] = ed2_w[t - 64];
    if (t < 3) sb2[t] = ed2_b[t];
    __syncthreads();

    float o0 = sb2[0], o1 = sb2[1], o2 = sb2[2];
    const float4* bd4 = (const float4*)(&g_Bd[gd * 64]);
    #pragma unroll
    for (int k4 = 0; k4 < 16; k4++) {
        float4 bv = bd4[k4];
        int k = k4 * 4;
        float h;
        h = fmaxf(sAs[k + 0] + bv.x + sb1[k + 0], 0.f);
        o0 = fmaf(h, sw2[(k + 0) * 3 + 0], o0); o1 = fmaf(h, sw2[(k + 0) * 3 + 1], o1); o2 = fmaf(h, sw2[(k + 0) * 3 + 2], o2);
        h = fmaxf(sAs[k + 1] + bv.y + sb1[k + 1], 0.f);
        o0 = fmaf(h, sw2[(k + 1) * 3 + 0], o0); o1 = fmaf(h, sw2[(k + 1) * 3 + 1], o1); o2 = fmaf(h, sw2[(k + 1) * 3 + 2], o2);
        h = fmaxf(sAs[k + 2] + bv.z + sb1[k + 2], 0.f);
        o0 = fmaf(h, sw2[(k + 2) * 3 + 0], o0); o1 = fmaf(h, sw2[(k + 2) * 3 + 1], o1); o2 = fmaf(h, sw2[(k + 2) * 3 + 2], o2);
        h = fmaxf(sAs[k + 3] + bv.w + sb1[k + 3], 0.f);
        o0 = fmaf(h, sw2[(k + 3) * 3 + 0], o0); o1 = fmaf(h, sw2[(k + 3) * 3 + 1], o1); o2 = fmaf(h, sw2[(k + 3) * 3 + 2], o2);
    }
    g_table[gs * MAXB + gd] = make_float4(o0, o1, o2, 0.f);
}

// ---------------------------------------------------------------------------
// Edge gather: 8 edges/thread, batched independent loads
// ---------------------------------------------------------------------------
__global__ void edge_gather_kernel(const int* __restrict__ src, const int* __restrict__ dst,
                                   const int* __restrict__ graph_id,
                                   float* __restrict__ out_edge, int E)
{
    int e = (blockIdx.x * blockDim.x + threadIdx.x) * 8;
    if (e >= E) return;
    if (e + 8 <= E) {
        int4 s0 = *(const int4*)(src + e);
        int4 s1 = *(const int4*)(src + e + 4);
        int4 d0 = *(const int4*)(dst + e);
        int4 d1 = *(const int4*)(dst + e + 4);
        int gs0 = graph_id[s0.x], gs1 = graph_id[s0.y], gs2 = graph_id[s0.z], gs3 = graph_id[s0.w];
        int gs4 = graph_id[s1.x], gs5 = graph_id[s1.y], gs6 = graph_id[s1.z], gs7 = graph_id[s1.w];
        int gd0 = graph_id[d0.x], gd1 = graph_id[d0.y], gd2 = graph_id[d0.z], gd3 = graph_id[d0.w];
        int gd4 = graph_id[d1.x], gd5 = graph_id[d1.y], gd6 = graph_id[d1.z], gd7 = graph_id[d1.w];
        float4 t0 = g_table[gs0 * MAXB + gd0];
        float4 t1 = g_table[gs1 * MAXB + gd1];
        float4 t2 = g_table[gs2 * MAXB + gd2];
        float4 t3 = g_table[gs3 * MAXB + gd3];
        float4 t4 = g_table[gs4 * MAXB + gd4];
        float4 t5 = g_table[gs5 * MAXB + gd5];
        float4 t6 = g_table[gs6 * MAXB + gd6];
        float4 t7 = g_table[gs7 * MAXB + gd7];
        float* o = out_edge + (size_t)e * 3;
        ((float4*)o)[0] = make_float4(t0.x, t0.y, t0.z, t1.x);
        ((float4*)o)[1] = make_float4(t1.y, t1.z, t2.x, t2.y);
        ((float4*)o)[2] = make_float4(t2.z, t3.x, t3.y, t3.z);
        ((float4*)o)[3] = make_float4(t4.x, t4.y, t4.z, t5.x);
        ((float4*)o)[4] = make_float4(t5.y, t5.z, t6.x, t6.y);
        ((float4*)o)[5] = make_float4(t6.z, t7.x, t7.y, t7.z);
    } else {
        for (int q = e; q < E; q++) {
            float4 t = g_table[graph_id[src[q]] * MAXB + graph_id[dst[q]]];
            out_edge[(size_t)q * 3 + 0] = t.x;
            out_edge[(size_t)q * 3 + 1] = t.y;
            out_edge[(size_t)q * 3 + 2] = t.z;
        }
    }
}

// ---------------------------------------------------------------------------
extern "C" void kernel_launch(void* const* d_in, const int* in_sizes, int n_in,
                              void* d_out, int out_size)
{
    const float* z        = (const float*)d_in[0];
    const float* node_emb = (const float*)d_in[1];
    const int*   graph_id = (const int*)  d_in[2];
    const int*   src      = (const int*)  d_in[3];
    const int*   dst      = (const int*)  d_in[4];
    const float* lp_w  = (const float*)d_in[5];
    const float* lp_b  = (const float*)d_in[6];
    const float* nep_w = (const float*)d_in[7];
    const float* nep_b = (const float*)d_in[8];
    const float* nd1_w = (const float*)d_in[9];
    const float* nd1_b = (const float*)d_in[10];
    const float* nd2_w = (const float*)d_in[11];
    const float* nd2_b = (const float*)d_in[12];
    const float* ed1_w = (const float*)d_in[13];
    const float* ed1_b = (const float*)d_in[14];
    const float* ed2_w = (const float*)d_in[15];
    const float* ed2_b = (const float*)d_in[16];
    const float* en1_w = (const float*)d_in[17];
    const float* en1_b = (const float*)d_in[18];
    const float* en2_w = (const float*)d_in[19];
    const float* en2_b = (const float*)d_in[20];
    const float* st1_w = (const float*)d_in[21];
    const float* st1_b = (const float*)d_in[22];
    const float* st2_w = (const float*)d_in[23];
    const float* st2_b = (const float*)d_in[24];

    const int B = in_sizes[0] / 32;
    const int N = in_sizes[1] / 128;
    const int E = in_sizes[3];

    float* out        = (float*)d_out;
    float* out_node   = out;
    float* out_edge   = out + (size_t)N * 4;
    float* out_energy = out + (size_t)N * 4 + (size_t)E * 3;
    float* out_stress = out_energy + (size_t)B * 2;

    cudaFuncSetAttribute(node_mma_kernel, cudaFuncAttributeMaxDynamicSharedMemorySize,
                         NODE_SMEM_BYTES);

    wconv_kernel<<<64, 256>>>(nep_w, nd1_w);

    prep_kernel<<<B, 128>>>(z, lp_w, lp_b, nd1_w, nd1_b, ed1_w,
                            en1_w, en1_b, en2_w, en2_b,
                            st1_w, st1_b, st2_w, st2_b,
                            out_energy, out_stress);

    edge_table_kernel<<<B, 256>>>(ed1_b, ed2_w, ed2_b);

    const int ntiles = (N + 127) / 128;
    const int grid = ntiles < 148 ? ntiles : 148;
    node_mma_kernel<<<grid, 512, NODE_SMEM_BYTES>>>(node_emb, graph_id,
                                                    nep_b, nd2_w, nd2_b,
                                                    out_node, N, ntiles);

    const int eth = (E + 7) / 8;
    edge_gather_kernel<<<(eth + 255) / 256, 256>>>(src, dst, graph_id, out_edge, E);
}